// round 8
// baseline (speedup 1.0000x reference)
#include <cuda_runtime.h>
#include <cuda_bf16.h>
#include <cstdint>

#define BATCH 16384
#define KD    1024
#define NOUT  289
#define H1D   256
#define H2D   128

// ---------------------------------------------------------------------------
// Device scratch (zero-initialized at load; Bt pad rows 289..319 stay 0).
// ---------------------------------------------------------------------------
__device__ float         g_cbias[NOUT];
__device__ __nv_bfloat16 g_Bthi[320 * KD];
__device__ __nv_bfloat16 g_Btlo[320 * KD];
__device__ __nv_bfloat16 g_Hhi[BATCH * H1D];
__device__ __nv_bfloat16 g_Hlo[BATCH * H1D];
__device__ __nv_bfloat16 g_W2thi[H2D * H1D];
__device__ __nv_bfloat16 g_W2tlo[H2D * H1D];
__device__ float         g_MS[BATCH * 16];
__device__ float         g_US[BATCH * 16];
__device__ float         g_ADD[BATCH];

// ---------------------------------------------------------------------------
// Helpers (base sm_103 PTX only: mma.sync / ldmatrix / cp.async)
// ---------------------------------------------------------------------------
static __device__ __forceinline__ uint32_t smem_u32(const void* p) {
    uint32_t a;
    asm("{ .reg .u64 t; cvta.to.shared.u64 t, %1; cvt.u32.u64 %0, t; }" : "=r"(a) : "l"(p));
    return a;
}
static __device__ __forceinline__ void cp16(uint32_t dst, const void* src) {
    asm volatile("cp.async.cg.shared.global [%0], [%1], 16;\n" :: "r"(dst), "l"(src));
}
#define CP_COMMIT() asm volatile("cp.async.commit_group;\n" ::: "memory")
#define CP_WAIT1()  asm volatile("cp.async.wait_group 1;\n" ::: "memory")
#define CP_WAIT2()  asm volatile("cp.async.wait_group 2;\n" ::: "memory")

#define LDSM4(r0, r1, r2, r3, addr) \
    asm volatile("ldmatrix.sync.aligned.m8n8.x4.shared.b16 {%0,%1,%2,%3}, [%4];" \
                 : "=r"(r0), "=r"(r1), "=r"(r2), "=r"(r3) : "r"(addr))

#define MMA16816(c, a, b) \
    asm volatile("mma.sync.aligned.m16n8k16.row.col.f32.bf16.bf16.f32 " \
                 "{%0,%1,%2,%3},{%4,%5,%6,%7},{%8,%9},{%0,%1,%2,%3};" \
                 : "+f"((c)[0]), "+f"((c)[1]), "+f"((c)[2]), "+f"((c)[3]) \
                 : "r"((a)[0]), "r"((a)[1]), "r"((a)[2]), "r"((a)[3]), \
                   "r"((b)[0]), "r"((b)[1]))

#define SWZ(x)   ((x) ^ (((x) >> 3) & 0x70))   // 128B-row swizzle (tail)
#define SWZ64(x) ((x) ^ (((x) >> 3) & 0x30))   // 64B-row swizzle (main, CK=32)

static __device__ __forceinline__ void split2(float v, __nv_bfloat16& h, __nv_bfloat16& l) {
    h = __float2bfloat16(v);
    l = __float2bfloat16(v - __bfloat162float(h));
}
static __device__ __forceinline__ uint32_t pack_bf2(__nv_bfloat16 a, __nv_bfloat16 b) {
    __nv_bfloat162 p; p.x = a; p.y = b;
    return *reinterpret_cast<uint32_t*>(&p);
}

// ---------------------------------------------------------------------------
// K0a: combined-tower GEMM, result written TRANSPOSED + SPLIT into Bt(hi/lo).
// Bt[n, kglob] = (Wm|Wu)[kglob, :256] @ W1half. blockIdx.z selects the tower.
// ---------------------------------------------------------------------------
__global__ __launch_bounds__(256) void k_combine_gemm(
    const float* __restrict__ Wm, const float* __restrict__ Wu,
    const float* __restrict__ W1)
{
    const float* A  = (blockIdx.z == 0) ? Wm : Wu;
    const float* Bw = (blockIdx.z == 0) ? W1 : (W1 + 256 * 256);
    int koff        = (blockIdx.z == 0) ? 0  : 512;
    const int lda = 257, ldb = 256, K = 256;

    __shared__ float As[16][64];
    __shared__ float Bs[16][64];
    int t = threadIdx.x;
    int tx = t & 15, ty = t >> 4;
    int m0 = blockIdx.y * 64, n0 = blockIdx.x * 64;
    float acc[4][4] = {};

    for (int k0 = 0; k0 < K; k0 += 16) {
        {
            int row = t >> 2;
            int kq = (t & 3) << 2;
            const float* ap = A + (m0 + row) * lda + k0 + kq;
            #pragma unroll
            for (int i = 0; i < 4; i++) As[kq + i][row] = ap[i];
        }
        {
            int kr = t >> 4;
            int nq = (t & 15) << 2;
            float4 v = *reinterpret_cast<const float4*>(Bw + (k0 + kr) * ldb + n0 + nq);
            *reinterpret_cast<float4*>(&Bs[kr][nq]) = v;
        }
        __syncthreads();
        #pragma unroll
        for (int kk = 0; kk < 16; kk++) {
            float a[4], b[4];
            #pragma unroll
            for (int i = 0; i < 4; i++) a[i] = As[kk][ty * 4 + i];
            #pragma unroll
            for (int j = 0; j < 4; j++) b[j] = Bs[kk][tx * 4 + j];
            #pragma unroll
            for (int i = 0; i < 4; i++)
                #pragma unroll
                for (int j = 0; j < 4; j++) acc[i][j] += a[i] * b[j];
        }
        __syncthreads();
    }
    #pragma unroll
    for (int i = 0; i < 4; i++)
        #pragma unroll
        for (int j = 0; j < 4; j++) {
            int kg = koff + m0 + ty * 4 + i;
            int nr = n0 + tx * 4 + j;
            __nv_bfloat16 h, l;
            split2(acc[i][j], h, l);
            g_Bthi[(size_t)nr * KD + kg] = h;
            g_Btlo[(size_t)nr * KD + kg] = l;
        }
}

// ---------------------------------------------------------------------------
// K0b: ms/us/additive rows of Bt + combined bias vector + W2t split.
// ---------------------------------------------------------------------------
__global__ void k_small(const float* __restrict__ Wm, const float* __restrict__ bm,
                        const float* __restrict__ Wu, const float* __restrict__ bu,
                        const float* __restrict__ W1, const float* __restrict__ b1,
                        const float* __restrict__ W2)
{
    int t = blockIdx.x * blockDim.x + threadIdx.x;
    if (t < KD * 16) {
        int k = t >> 4, d = t & 15;
        float s = 0.f;
        __nv_bfloat16 h, l;
        if (k < 512) {
            #pragma unroll
            for (int i = 0; i < 16; i++) s += Wm[k * 257 + i * 16 + d];
            split2(s, h, l);
            g_Bthi[(size_t)(256 + d) * KD + k] = h;
            g_Btlo[(size_t)(256 + d) * KD + k] = l;
            if (d == 0) {
                split2(Wm[k * 257 + 256], h, l);
                g_Bthi[(size_t)288 * KD + k] = h;
                g_Btlo[(size_t)288 * KD + k] = l;
            }
        } else {
            int ku = k - 512;
            #pragma unroll
            for (int i = 0; i < 16; i++) s += Wu[ku * 257 + i * 16 + d];
            split2(s, h, l);
            g_Bthi[(size_t)(272 + d) * KD + k] = h;
            g_Btlo[(size_t)(272 + d) * KD + k] = l;
            if (d == 0) {
                split2(Wu[ku * 257 + 256], h, l);
                g_Bthi[(size_t)288 * KD + k] = h;
                g_Btlo[(size_t)288 * KD + k] = l;
            }
        }
        return;
    }
    int c = t - KD * 16;
    if (c < NOUT) {
        float v;
        if (c < 256) {
            v = b1[c];
            for (int j = 0; j < 256; j++) v += bm[j] * W1[j * 256 + c];
            for (int j = 0; j < 256; j++) v += bu[j] * W1[(256 + j) * 256 + c];
        } else if (c < 272) {
            int d = c - 256; v = 0.f;
            #pragma unroll
            for (int i = 0; i < 16; i++) v += bm[i * 16 + d];
        } else if (c < 288) {
            int d = c - 272; v = 0.f;
            #pragma unroll
            for (int i = 0; i < 16; i++) v += bu[i * 16 + d];
        } else {
            v = bm[256] + bu[256];
        }
        g_cbias[c] = v;
        return;
    }
    int j = c - NOUT;
    if (j < H2D * H1D) {
        int r = j >> 8, cc = j & 255;        // W2t[r][cc] = W2[cc][r]
        __nv_bfloat16 h, l;
        split2(W2[cc * H2D + r], h, l);
        g_W2thi[j] = h; g_W2tlo[j] = l;
    }
}

// ---------------------------------------------------------------------------
// K1: main mma.sync GEMM with fused fp32->bf16 hi/lo split of A.
// C[16384, 320] = A[16384,1024 fp32] (x) Bt(hi/lo)[320,1024]^T, 3 split terms.
// Grid (2 nblk, 128 mblk), CTA tile 128x160, 256 thr (8 warps 4Mx2N, warp 32x80),
// K-chunk=32, 3-stage, 2 CTAs/SM (108KB smem each) for barrier-latency hiding.
// ---------------------------------------------------------------------------
#define CK         32
#define NCHUNK     32
#define AHI_OFF    0
#define ALO_OFF    8192
#define BHI_OFF    16384
#define BLO_OFF    26624
#define MAIN_STAGE 36864                      // 8+8+10+10 KB
#define SMEM_MAIN  (3 * MAIN_STAGE)           // 108 KB

static __device__ __forceinline__ void ldg_a(float4* p, int ch, int m0, int t,
                                             const float* __restrict__ mv,
                                             const float* __restrict__ uv)
{
    int kc = ch * CK;
    const float* base = (kc < 512) ? (mv + kc) : (uv + kc - 512);
    #pragma unroll
    for (int l = 0; l < 4; l++) {
        int f = t + l * 256;
        int row = f >> 3, q = f & 7;
        p[l] = *reinterpret_cast<const float4*>(base + (size_t)(m0 + row) * 512 + q * 4);
    }
}

static __device__ __forceinline__ void sts_a(const float4* p, uint32_t stg, int t)
{
    #pragma unroll
    for (int l = 0; l < 4; l++) {
        int f = t + l * 256;
        int row = f >> 3, q = f & 7;
        __nv_bfloat16 h0, l0, h1, l1, h2, l2, h3, l3;
        split2(p[l].x, h0, l0); split2(p[l].y, h1, l1);
        split2(p[l].z, h2, l2); split2(p[l].w, h3, l3);
        uint32_t hi0 = pack_bf2(h0, h1), hi1 = pack_bf2(h2, h3);
        uint32_t lo0 = pack_bf2(l0, l1), lo1 = pack_bf2(l2, l3);
        uint32_t off = SWZ64(row * 64 + q * 8);
        asm volatile("st.shared.v2.b32 [%0], {%1,%2};"
                     :: "r"(stg + AHI_OFF + off), "r"(hi0), "r"(hi1) : "memory");
        asm volatile("st.shared.v2.b32 [%0], {%1,%2};"
                     :: "r"(stg + ALO_OFF + off), "r"(lo0), "r"(lo1) : "memory");
    }
}

static __device__ __forceinline__ void cp_b(uint32_t stg, int ch, int nb0, int t)
{
    int kc = ch * CK;
    #pragma unroll
    for (int l = 0; l < 5; l++) {
        int f = t + l * 256;                  // 0..1279: 640 hi + 640 lo units
        int lobuf = f >= 640;
        int fr = lobuf ? f - 640 : f;
        int row = fr >> 2, u = fr & 3;
        const __nv_bfloat16* src = (lobuf ? g_Btlo : g_Bthi)
                                   + (size_t)(nb0 + row) * KD + kc + u * 8;
        cp16(stg + (lobuf ? BLO_OFF : BHI_OFF) + SWZ64(row * 64 + u * 16), src);
    }
}

static __device__ __forceinline__ void seg_mma(uint32_t ab, uint32_t bb, int ks,
                                               int wm, int wn,
                                               int a_row, int a_koff,
                                               int b_row, int b_koff,
                                               float c[2][10][4])
{
    uint32_t a[2][4];
    #pragma unroll
    for (int mt = 0; mt < 2; mt++)
        LDSM4(a[mt][0], a[mt][1], a[mt][2], a[mt][3],
              ab + SWZ64((wm * 32 + mt * 16 + a_row) * 64 + ks * 32 + a_koff));
    #pragma unroll
    for (int jp = 0; jp < 5; jp++) {
        uint32_t b0[2], b1[2];
        LDSM4(b0[0], b0[1], b1[0], b1[1],
              bb + SWZ64((wn * 80 + jp * 16 + b_row) * 64 + ks * 32 + b_koff));
        #pragma unroll
        for (int mt = 0; mt < 2; mt++) {
            MMA16816(c[mt][2 * jp],     a[mt], b0);
            MMA16816(c[mt][2 * jp + 1], a[mt], b1);
        }
    }
}

__global__ __launch_bounds__(256, 2) void k_mma_main(
    const float* __restrict__ mv, const float* __restrict__ uv)
{
    extern __shared__ char smem[];
    uint32_t sb = smem_u32(smem);
    int t = threadIdx.x;
    int lane = t & 31, wid = t >> 5;
    int wm = wid & 3, wn = wid >> 2;          // 4M x 2N warps
    int nb0 = blockIdx.x * 160;
    int m0  = blockIdx.y * 128;

    float c[2][10][4];
    #pragma unroll
    for (int i = 0; i < 2; i++)
        #pragma unroll
        for (int j = 0; j < 10; j++)
            #pragma unroll
            for (int q = 0; q < 4; q++) c[i][j][q] = 0.f;

    int a_row  = (lane & 15);
    int a_koff = (lane >> 4) * 16;
    int b_row  = ((lane >> 4) & 1) * 8 + (lane & 7);
    int b_koff = ((lane >> 3) & 1) * 16;

    // Prologue: chunks 0,1 (A via LDG+split+STS, B via cp.async).
    {
        float4 q0[4], q1[4];
        ldg_a(q0, 0, m0, t, mv, uv);
        ldg_a(q1, 1, m0, t, mv, uv);
        cp_b(sb + 0 * MAIN_STAGE, 0, nb0, t); CP_COMMIT();
        cp_b(sb + 1 * MAIN_STAGE, 1, nb0, t); CP_COMMIT();
        sts_a(q0, sb + 0 * MAIN_STAGE, t);
        sts_a(q1, sb + 1 * MAIN_STAGE, t);
    }

    float4 pf[4];
    #pragma unroll 1
    for (int ic = 0; ic < NCHUNK; ic++) {
        bool pfv = (ic + 2 < NCHUNK);
        if (pfv) ldg_a(pf, ic + 2, m0, t, mv, uv);   // latency hidden by mma below
        CP_WAIT1();                                   // B(ic) arrived
        __syncthreads();                              // stage (ic+2)%3 readers done
        if (pfv) cp_b(sb + ((ic + 2) % 3) * MAIN_STAGE, ic + 2, nb0, t);
        CP_COMMIT();

        uint32_t stg = sb + (ic % 3) * MAIN_STAGE;
        seg_mma(stg + AHI_OFF, stg + BHI_OFF, 0, wm, wn, a_row, a_koff, b_row, b_koff, c);
        seg_mma(stg + ALO_OFF, stg + BHI_OFF, 0, wm, wn, a_row, a_koff, b_row, b_koff, c);
        seg_mma(stg + AHI_OFF, stg + BLO_OFF, 0, wm, wn, a_row, a_koff, b_row, b_koff, c);
        if (pfv) sts_a(pf, sb + ((ic + 2) % 3) * MAIN_STAGE, t);
        seg_mma(stg + AHI_OFF, stg + BHI_OFF, 1, wm, wn, a_row, a_koff, b_row, b_koff, c);
        seg_mma(stg + ALO_OFF, stg + BHI_OFF, 1, wm, wn, a_row, a_koff, b_row, b_koff, c);
        seg_mma(stg + AHI_OFF, stg + BLO_OFF, 1, wm, wn, a_row, a_koff, b_row, b_koff, c);
    }

    // Epilogue: bias, relu, split / route.
    #pragma unroll
    for (int mt = 0; mt < 2; mt++) {
        int rbase = m0 + wm * 32 + mt * 16 + (lane >> 2);
        #pragma unroll
        for (int half = 0; half < 2; half++) {
            int m = rbase + half * 8;
            #pragma unroll
            for (int j = 0; j < 10; j++) {
                int n = nb0 + wn * 80 + j * 8 + (lane & 3) * 2;
                float v0 = c[mt][j][half * 2 + 0] + g_cbias[n < NOUT ? n : 0];
                float v1 = c[mt][j][half * 2 + 1] + g_cbias[(n + 1) < NOUT ? (n + 1) : 0];
                if (n < 256) {
                    v0 = fmaxf(v0, 0.f); v1 = fmaxf(v1, 0.f);
                    __nv_bfloat16 h0, l0, h1, l1;
                    split2(v0, h0, l0); split2(v1, h1, l1);
                    *reinterpret_cast<uint32_t*>(&g_Hhi[(size_t)m * H1D + n]) = pack_bf2(h0, h1);
                    *reinterpret_cast<uint32_t*>(&g_Hlo[(size_t)m * H1D + n]) = pack_bf2(l0, l1);
                } else {
                    #pragma unroll
                    for (int e = 0; e < 2; e++) {
                        int ne = n + e;
                        float ve = e ? v1 : v0;
                        if (ne < 272)       g_MS[m * 16 + ne - 256] = ve;
                        else if (ne < 288)  g_US[m * 16 + ne - 272] = ve;
                        else if (ne == 288) g_ADD[m] = ve;
                    }
                }
            }
        }
    }
}

// ---------------------------------------------------------------------------
// K2: tail mma.sync GEMM + final reduce.
// C[16384,128] = Hcat[16384,768] @ W2tcat[128,768]^T; out = relu(.)·W3 + ...
// Grid 128 CTAs (M=128 each), 8 warps, warp tile 16x128.
// ---------------------------------------------------------------------------
#define TAIL_STAGE 32768                      // 16KB A + 16KB B
#define SMEM_TAIL  (3 * TAIL_STAGE)

static __device__ __forceinline__ void issue_tail(uint32_t sb, int ic, int st,
                                                  int m0, int t)
{
    int seg = ic >> 2;
    int kc  = (ic & 3) * 64;
    const __nv_bfloat16 *Ap, *Bp;
    if (seg == 0)      { Ap = g_Hhi;   Bp = g_W2thi; }
    else if (seg == 1) { Ap = g_Hlo;   Bp = g_W2thi; }
    else               { Ap = g_Hhi;   Bp = g_W2tlo; }
    uint32_t ab = sb + st * TAIL_STAGE;
    uint32_t bb = ab + 16384;
    #pragma unroll
    for (int l = 0; l < 4; l++) {
        int f = t + l * 256;
        int row = f >> 3, kq = (f & 7) * 8;
        cp16(ab + SWZ(row * 128 + kq * 2), Ap + (size_t)(m0 + row) * H1D + kc + kq);
    }
    #pragma unroll
    for (int l = 0; l < 4; l++) {
        int f = t + l * 256;
        int row = f >> 3, kq = (f & 7) * 8;
        cp16(bb + SWZ(row * 128 + kq * 2), Bp + (size_t)row * H1D + kc + kq);
    }
}

__global__ __launch_bounds__(256, 1) void k_mma_tail(
    const float* __restrict__ b2, const float* __restrict__ W3,
    const float* __restrict__ b3, float* __restrict__ out)
{
    extern __shared__ char smem[];
    __shared__ float b2s[128];
    __shared__ float w3s[128];
    uint32_t sb = smem_u32(smem);
    int t = threadIdx.x;
    int lane = t & 31, w = t >> 5;
    int m0 = blockIdx.x * 128;

    if (t < 128) { b2s[t] = b2[t]; w3s[t] = W3[t]; }

    float c[16][4];
    #pragma unroll
    for (int j = 0; j < 16; j++)
        #pragma unroll
        for (int q = 0; q < 4; q++) c[j][q] = 0.f;

    const int NC = 12;
    issue_tail(sb, 0, 0, m0, t); CP_COMMIT();
    issue_tail(sb, 1, 1, m0, t); CP_COMMIT();

    int a_row  = (lane & 15);
    int a_koff = (lane >> 4) * 16;
    int b_row  = ((lane >> 4) & 1) * 8 + (lane & 7);
    int b_koff = ((lane >> 3) & 1) * 16;

    #pragma unroll 1
    for (int ic = 0; ic < NC; ic++) {
        __syncthreads();
        if (ic + 2 < NC) issue_tail(sb, ic + 2, (ic + 2) % 3, m0, t);
        CP_COMMIT();
        CP_WAIT2();
        __syncthreads();

        uint32_t ab = sb + (ic % 3) * TAIL_STAGE;
        uint32_t bb = ab + 16384;
        #pragma unroll
        for (int ks = 0; ks < 4; ks++) {
            uint32_t a[4], b[16][2];
            LDSM4(a[0], a[1], a[2], a[3],
                  ab + SWZ((w * 16 + a_row) * 128 + ks * 32 + a_koff));
            #pragma unroll
            for (int jp = 0; jp < 8; jp++)
                LDSM4(b[2 * jp][0], b[2 * jp][1], b[2 * jp + 1][0], b[2 * jp + 1][1],
                      bb + SWZ((jp * 16 + b_row) * 128 + ks * 32 + b_koff));
            #pragma unroll
            for (int j = 0; j < 16; j++)
                MMA16816(c[j], a, b[j]);
        }
    }

    // Epilogue: relu(c + b2) dot W3, reduce across the 4 lanes sharing a row.
    float p0 = 0.f, p1 = 0.f;
    #pragma unroll
    for (int j = 0; j < 16; j++) {
        int n = j * 8 + (lane & 3) * 2;
        p0 += fmaxf(c[j][0] + b2s[n],     0.f) * w3s[n];
        p0 += fmaxf(c[j][1] + b2s[n + 1], 0.f) * w3s[n + 1];
        p1 += fmaxf(c[j][2] + b2s[n],     0.f) * w3s[n];
        p1 += fmaxf(c[j][3] + b2s[n + 1], 0.f) * w3s[n + 1];
    }
    p0 += __shfl_xor_sync(0xFFFFFFFF, p0, 1);
    p0 += __shfl_xor_sync(0xFFFFFFFF, p0, 2);
    p1 += __shfl_xor_sync(0xFFFFFFFF, p1, 1);
    p1 += __shfl_xor_sync(0xFFFFFFFF, p1, 2);

    if ((lane & 3) == 0) {
        float b3v = b3[0];
        #pragma unroll
        for (int half = 0; half < 2; half++) {
            int m = m0 + w * 16 + (lane >> 2) + half * 8;
            float s = (half ? p1 : p0) + b3v + g_ADD[m];
            #pragma unroll
            for (int i = 0; i < 16; i++) s += g_MS[m * 16 + i] * g_US[m * 16 + i];
            out[m] = s;
        }
    }
}

// ---------------------------------------------------------------------------
extern "C" void kernel_launch(void* const* d_in, const int* in_sizes, int n_in,
                              void* d_out, int out_size)
{
    const float* mv = (const float*)d_in[0];
    const float* uv = (const float*)d_in[1];
    const float* Wm = (const float*)d_in[2];
    const float* bm = (const float*)d_in[3];
    const float* Wu = (const float*)d_in[4];
    const float* bu = (const float*)d_in[5];
    const float* W1 = (const float*)d_in[6];
    const float* b1 = (const float*)d_in[7];
    const float* W2 = (const float*)d_in[8];
    const float* b2 = (const float*)d_in[9];
    const float* W3 = (const float*)d_in[10];
    const float* b3 = (const float*)d_in[11];
    float* out = (float*)d_out;

    cudaFuncSetAttribute(k_mma_main, cudaFuncAttributeMaxDynamicSharedMemorySize, SMEM_MAIN);
    cudaFuncSetAttribute(k_mma_tail, cudaFuncAttributeMaxDynamicSharedMemorySize, SMEM_TAIL);

    // Weight precompute (fresh every call). Bt written directly split+transposed.
    k_combine_gemm<<<dim3(4, 8, 2), 256>>>(Wm, Wu, W1);
    k_small<<<(KD * 16 + NOUT + H2D * H1D + 255) / 256, 256>>>(Wm, bm, Wu, bu, W1, b1, W2);

    // Main tensor-core GEMM, 2 CTAs/SM, one wave of 256 CTAs.
    k_mma_main<<<dim3(2, BATCH / 128), 256, SMEM_MAIN>>>(mv, uv);

    // Tail tensor-core GEMM + final reduction.
    k_mma_tail<<<BATCH / 128, 256, SMEM_TAIL>>>(b2, W3, b3, out);
}

// round 9
// speedup vs baseline: 1.2315x; 1.2315x over previous
#include <cuda_runtime.h>
#include <cuda_bf16.h>
#include <cstdint>

#define BATCH 16384
#define KD    1024
#define NOUT  289
#define H1D   256
#define H2D   128

// ---------------------------------------------------------------------------
// Device scratch (zero-initialized at load; Bt pad rows 289..319 stay 0).
// ---------------------------------------------------------------------------
__device__ float         g_cbias[NOUT];
__device__ __nv_bfloat16 g_Bthi[320 * KD];
__device__ __nv_bfloat16 g_Btlo[320 * KD];
__device__ __nv_bfloat16 g_Hhi[BATCH * H1D];
__device__ __nv_bfloat16 g_Hlo[BATCH * H1D];
__device__ __nv_bfloat16 g_W2thi[H2D * H1D];
__device__ __nv_bfloat16 g_W2tlo[H2D * H1D];
__device__ float         g_MS[BATCH * 16];
__device__ float         g_US[BATCH * 16];
__device__ float         g_ADD[BATCH];

// ---------------------------------------------------------------------------
// Helpers (base sm_103 PTX only: mma.sync / ldmatrix / cp.async)
// ---------------------------------------------------------------------------
static __device__ __forceinline__ uint32_t smem_u32(const void* p) {
    uint32_t a;
    asm("{ .reg .u64 t; cvta.to.shared.u64 t, %1; cvt.u32.u64 %0, t; }" : "=r"(a) : "l"(p));
    return a;
}
static __device__ __forceinline__ void cp16(uint32_t dst, const void* src) {
    asm volatile("cp.async.cg.shared.global [%0], [%1], 16;\n" :: "r"(dst), "l"(src));
}
#define CP_COMMIT() asm volatile("cp.async.commit_group;\n" ::: "memory")
#define CP_WAIT1()  asm volatile("cp.async.wait_group 1;\n" ::: "memory")
#define CP_WAIT2()  asm volatile("cp.async.wait_group 2;\n" ::: "memory")

#define LDSM4(r0, r1, r2, r3, addr) \
    asm volatile("ldmatrix.sync.aligned.m8n8.x4.shared.b16 {%0,%1,%2,%3}, [%4];" \
                 : "=r"(r0), "=r"(r1), "=r"(r2), "=r"(r3) : "r"(addr))

#define MMA16816(c, a, b) \
    asm volatile("mma.sync.aligned.m16n8k16.row.col.f32.bf16.bf16.f32 " \
                 "{%0,%1,%2,%3},{%4,%5,%6,%7},{%8,%9},{%0,%1,%2,%3};" \
                 : "+f"((c)[0]), "+f"((c)[1]), "+f"((c)[2]), "+f"((c)[3]) \
                 : "r"((a)[0]), "r"((a)[1]), "r"((a)[2]), "r"((a)[3]), \
                   "r"((b)[0]), "r"((b)[1]))

#define SWZ(x)   ((x) ^ (((x) >> 3) & 0x70))   // 128B-row swizzle (tail)
#define SWZ64(x) ((x) ^ (((x) >> 3) & 0x30))   // 64B-row swizzle (main, CK=32)

static __device__ __forceinline__ void split2(float v, __nv_bfloat16& h, __nv_bfloat16& l) {
    h = __float2bfloat16(v);
    l = __float2bfloat16(v - __bfloat162float(h));
}
static __device__ __forceinline__ uint32_t pack_bf2(__nv_bfloat16 a, __nv_bfloat16 b) {
    __nv_bfloat162 p; p.x = a; p.y = b;
    return *reinterpret_cast<uint32_t*>(&p);
}

// ---------------------------------------------------------------------------
// K0: merged precompute. Blocks 0..63: combined-tower GEMM written transposed
// + split into Bt(hi/lo). Blocks 64..257: ms/us/add rows + bias + W2t split.
// ---------------------------------------------------------------------------
__global__ __launch_bounds__(256) void k_pre(
    const float* __restrict__ Wm, const float* __restrict__ bm,
    const float* __restrict__ Wu, const float* __restrict__ bu,
    const float* __restrict__ W1, const float* __restrict__ b1,
    const float* __restrict__ W2)
{
    __shared__ float As[16][64];
    __shared__ float Bs[16][64];

    if (blockIdx.x < 64) {
        // ---- combine GEMM: Bt[n, kglob] = (Wm|Wu)[kglob, :256] @ W1half ----
        int z   = blockIdx.x >> 5;            // tower
        int rem = blockIdx.x & 31;            // 4 nblk x 8 mblk
        const float* A  = (z == 0) ? Wm : Wu;
        const float* Bw = (z == 0) ? W1 : (W1 + 256 * 256);
        int koff        = (z == 0) ? 0  : 512;
        const int lda = 257, ldb = 256, K = 256;

        int t = threadIdx.x;
        int tx = t & 15, ty = t >> 4;
        int n0 = (rem & 3) * 64, m0 = (rem >> 2) * 64;
        float acc[4][4] = {};

        for (int k0 = 0; k0 < K; k0 += 16) {
            {
                int row = t >> 2;
                int kq = (t & 3) << 2;
                const float* ap = A + (m0 + row) * lda + k0 + kq;
                #pragma unroll
                for (int i = 0; i < 4; i++) As[kq + i][row] = ap[i];
            }
            {
                int kr = t >> 4;
                int nq = (t & 15) << 2;
                float4 v = *reinterpret_cast<const float4*>(Bw + (k0 + kr) * ldb + n0 + nq);
                *reinterpret_cast<float4*>(&Bs[kr][nq]) = v;
            }
            __syncthreads();
            #pragma unroll
            for (int kk = 0; kk < 16; kk++) {
                float a[4], b[4];
                #pragma unroll
                for (int i = 0; i < 4; i++) a[i] = As[kk][ty * 4 + i];
                #pragma unroll
                for (int j = 0; j < 4; j++) b[j] = Bs[kk][tx * 4 + j];
                #pragma unroll
                for (int i = 0; i < 4; i++)
                    #pragma unroll
                    for (int j = 0; j < 4; j++) acc[i][j] += a[i] * b[j];
            }
            __syncthreads();
        }
        #pragma unroll
        for (int i = 0; i < 4; i++)
            #pragma unroll
            for (int j = 0; j < 4; j++) {
                int kg = koff + m0 + ty * 4 + i;
                int nr = n0 + tx * 4 + j;
                __nv_bfloat16 h, l;
                split2(acc[i][j], h, l);
                g_Bthi[(size_t)nr * KD + kg] = h;
                g_Btlo[(size_t)nr * KD + kg] = l;
            }
        return;
    }

    // ---- small part ----
    int t = (blockIdx.x - 64) * 256 + threadIdx.x;
    if (t < KD * 16) {
        int k = t >> 4, d = t & 15;
        float s = 0.f;
        __nv_bfloat16 h, l;
        if (k < 512) {
            #pragma unroll
            for (int i = 0; i < 16; i++) s += Wm[k * 257 + i * 16 + d];
            split2(s, h, l);
            g_Bthi[(size_t)(256 + d) * KD + k] = h;
            g_Btlo[(size_t)(256 + d) * KD + k] = l;
            if (d == 0) {
                split2(Wm[k * 257 + 256], h, l);
                g_Bthi[(size_t)288 * KD + k] = h;
                g_Btlo[(size_t)288 * KD + k] = l;
            }
        } else {
            int ku = k - 512;
            #pragma unroll
            for (int i = 0; i < 16; i++) s += Wu[ku * 257 + i * 16 + d];
            split2(s, h, l);
            g_Bthi[(size_t)(272 + d) * KD + k] = h;
            g_Btlo[(size_t)(272 + d) * KD + k] = l;
            if (d == 0) {
                split2(Wu[ku * 257 + 256], h, l);
                g_Bthi[(size_t)288 * KD + k] = h;
                g_Btlo[(size_t)288 * KD + k] = l;
            }
        }
        return;
    }
    int c = t - KD * 16;
    if (c < NOUT) {
        float v;
        if (c < 256) {
            v = b1[c];
            for (int j = 0; j < 256; j++) v += bm[j] * W1[j * 256 + c];
            for (int j = 0; j < 256; j++) v += bu[j] * W1[(256 + j) * 256 + c];
        } else if (c < 272) {
            int d = c - 256; v = 0.f;
            #pragma unroll
            for (int i = 0; i < 16; i++) v += bm[i * 16 + d];
        } else if (c < 288) {
            int d = c - 272; v = 0.f;
            #pragma unroll
            for (int i = 0; i < 16; i++) v += bu[i * 16 + d];
        } else {
            v = bm[256] + bu[256];
        }
        g_cbias[c] = v;
        return;
    }
    int j = c - NOUT;
    if (j < H2D * H1D) {
        int r = j >> 8, cc = j & 255;        // W2t[r][cc] = W2[cc][r]
        __nv_bfloat16 h, l;
        split2(W2[cc * H2D + r], h, l);
        g_W2thi[j] = h; g_W2tlo[j] = l;
    }
}

// ---------------------------------------------------------------------------
// K1: main mma.sync GEMM with fused fp32->bf16 hi/lo split of A.
// C[16384, 320] = A[16384,1024 fp32] (x) Bt(hi/lo)[320,1024]^T, 3 split terms.
// 128 CTAs (one wave), 512 thr (16 warps, 4M x 4N, warp 32x80), K-chunk=32,
// 3-stage pipeline. A/Bhi fragments held in registers across split terms.
// ---------------------------------------------------------------------------
#define CK         32
#define NCHUNK     32
#define AHI_OFF    0
#define ALO_OFF    8192
#define BHI_OFF    16384
#define BLO_OFF    36864
#define MAIN_STAGE 57344                      // 8+8+20+20 KB
#define SMEM_MAIN  (3 * MAIN_STAGE)           // 168 KB

static __device__ __forceinline__ void ldg_a(float4* p, int ch, int m0, int t,
                                             const float* __restrict__ mv,
                                             const float* __restrict__ uv)
{
    int kc = ch * CK;
    const float* base = (kc < 512) ? (mv + kc) : (uv + kc - 512);
    #pragma unroll
    for (int l = 0; l < 2; l++) {
        int f = t + l * 512;
        int row = f >> 3, q = f & 7;
        p[l] = *reinterpret_cast<const float4*>(base + (size_t)(m0 + row) * 512 + q * 4);
    }
}

static __device__ __forceinline__ void sts_a(const float4* p, uint32_t stg, int t)
{
    #pragma unroll
    for (int l = 0; l < 2; l++) {
        int f = t + l * 512;
        int row = f >> 3, q = f & 7;
        __nv_bfloat16 h0, l0, h1, l1, h2, l2, h3, l3;
        split2(p[l].x, h0, l0); split2(p[l].y, h1, l1);
        split2(p[l].z, h2, l2); split2(p[l].w, h3, l3);
        uint32_t hi0 = pack_bf2(h0, h1), hi1 = pack_bf2(h2, h3);
        uint32_t lo0 = pack_bf2(l0, l1), lo1 = pack_bf2(l2, l3);
        uint32_t off = SWZ64(row * 64 + q * 8);
        asm volatile("st.shared.v2.b32 [%0], {%1,%2};"
                     :: "r"(stg + AHI_OFF + off), "r"(hi0), "r"(hi1) : "memory");
        asm volatile("st.shared.v2.b32 [%0], {%1,%2};"
                     :: "r"(stg + ALO_OFF + off), "r"(lo0), "r"(lo1) : "memory");
    }
}

static __device__ __forceinline__ void cp_b(uint32_t stg, int ch, int t)
{
    int kc = ch * CK;
    #pragma unroll
    for (int l = 0; l < 5; l++) {
        int f = t + l * 512;                  // 0..2559: 1280 hi + 1280 lo units
        int lobuf = f >= 1280;
        int fr = lobuf ? f - 1280 : f;
        int row = fr >> 2, u = fr & 3;
        const __nv_bfloat16* src = (lobuf ? g_Btlo : g_Bthi) + (size_t)row * KD + kc + u * 8;
        cp16(stg + (lobuf ? BLO_OFF : BHI_OFF) + SWZ64(row * 64 + u * 16), src);
    }
}

__global__ __launch_bounds__(512, 1) void k_mma_main(
    const float* __restrict__ mv, const float* __restrict__ uv)
{
    extern __shared__ char smem[];
    uint32_t sb = smem_u32(smem);
    int t = threadIdx.x;
    int lane = t & 31, wid = t >> 5;
    int wm = wid & 3, wn = wid >> 2;          // 4M x 4N warps
    int m0 = blockIdx.x * 128;

    float c[2][10][4];
    #pragma unroll
    for (int i = 0; i < 2; i++)
        #pragma unroll
        for (int j = 0; j < 10; j++)
            #pragma unroll
            for (int q = 0; q < 4; q++) c[i][j][q] = 0.f;

    int a_row  = (lane & 15);
    int a_koff = (lane >> 4) * 16;
    int b_row  = ((lane >> 4) & 1) * 8 + (lane & 7);
    int b_koff = ((lane >> 3) & 1) * 16;

    // Prologue: chunks 0,1 (A via LDG+split+STS, B via cp.async).
    {
        float4 q0[2], q1[2];
        ldg_a(q0, 0, m0, t, mv, uv);
        ldg_a(q1, 1, m0, t, mv, uv);
        cp_b(sb + 0 * MAIN_STAGE, 0, t); CP_COMMIT();
        cp_b(sb + 1 * MAIN_STAGE, 1, t); CP_COMMIT();
        sts_a(q0, sb + 0 * MAIN_STAGE, t);
        sts_a(q1, sb + 1 * MAIN_STAGE, t);
    }

    float4 pf[2];
    #pragma unroll 1
    for (int ic = 0; ic < NCHUNK; ic++) {
        bool pfv = (ic + 2 < NCHUNK);
        if (pfv) ldg_a(pf, ic + 2, m0, t, mv, uv);   // latency hidden by mma below
        CP_WAIT1();                                   // B(ic) arrived
        __syncthreads();                              // stage (ic+2)%3 readers done
        if (pfv) cp_b(sb + ((ic + 2) % 3) * MAIN_STAGE, ic + 2, t);
        CP_COMMIT();

        uint32_t stg = sb + (ic % 3) * MAIN_STAGE;
        #pragma unroll
        for (int ks = 0; ks < 2; ks++) {
            // A fragments loaded ONCE per ks, reused across the 3 split terms.
            uint32_t ahi[2][4], alo[2][4];
            #pragma unroll
            for (int mt = 0; mt < 2; mt++) {
                uint32_t ra = SWZ64((wm * 32 + mt * 16 + a_row) * 64 + ks * 32 + a_koff);
                LDSM4(ahi[mt][0], ahi[mt][1], ahi[mt][2], ahi[mt][3], stg + AHI_OFF + ra);
                LDSM4(alo[mt][0], alo[mt][1], alo[mt][2], alo[mt][3], stg + ALO_OFF + ra);
            }
            #pragma unroll
            for (int jp = 0; jp < 5; jp++) {
                uint32_t rb = SWZ64((wn * 80 + jp * 16 + b_row) * 64 + ks * 32 + b_koff);
                uint32_t b0[2], b1[2];
                LDSM4(b0[0], b0[1], b1[0], b1[1], stg + BHI_OFF + rb);   // Bhi
                #pragma unroll
                for (int mt = 0; mt < 2; mt++) {
                    MMA16816(c[mt][2 * jp],     ahi[mt], b0);
                    MMA16816(c[mt][2 * jp + 1], ahi[mt], b1);
                    MMA16816(c[mt][2 * jp],     alo[mt], b0);
                    MMA16816(c[mt][2 * jp + 1], alo[mt], b1);
                }
                LDSM4(b0[0], b0[1], b1[0], b1[1], stg + BLO_OFF + rb);   // Blo
                #pragma unroll
                for (int mt = 0; mt < 2; mt++) {
                    MMA16816(c[mt][2 * jp],     ahi[mt], b0);
                    MMA16816(c[mt][2 * jp + 1], ahi[mt], b1);
                }
            }
            if (ks == 0 && pfv) sts_a(pf, sb + ((ic + 2) % 3) * MAIN_STAGE, t);
        }
    }

    // Epilogue: bias, relu, split / route.
    #pragma unroll
    for (int mt = 0; mt < 2; mt++) {
        int rbase = m0 + wm * 32 + mt * 16 + (lane >> 2);
        #pragma unroll
        for (int half = 0; half < 2; half++) {
            int m = rbase + half * 8;
            #pragma unroll
            for (int j = 0; j < 10; j++) {
                int n = wn * 80 + j * 8 + (lane & 3) * 2;
                float v0 = c[mt][j][half * 2 + 0] + g_cbias[n < NOUT ? n : 0];
                float v1 = c[mt][j][half * 2 + 1] + g_cbias[(n + 1) < NOUT ? (n + 1) : 0];
                if (n < 256) {
                    v0 = fmaxf(v0, 0.f); v1 = fmaxf(v1, 0.f);
                    __nv_bfloat16 h0, l0, h1, l1;
                    split2(v0, h0, l0); split2(v1, h1, l1);
                    *reinterpret_cast<uint32_t*>(&g_Hhi[(size_t)m * H1D + n]) = pack_bf2(h0, h1);
                    *reinterpret_cast<uint32_t*>(&g_Hlo[(size_t)m * H1D + n]) = pack_bf2(l0, l1);
                } else {
                    #pragma unroll
                    for (int e = 0; e < 2; e++) {
                        int ne = n + e;
                        float ve = e ? v1 : v0;
                        if (ne < 272)       g_MS[m * 16 + ne - 256] = ve;
                        else if (ne < 288)  g_US[m * 16 + ne - 272] = ve;
                        else if (ne == 288) g_ADD[m] = ve;
                    }
                }
            }
        }
    }
}

// ---------------------------------------------------------------------------
// K2: tail mma.sync GEMM + final reduce, re-tiled for occupancy.
// C[16384,128] = Hcat[16384,768] @ W2tcat[128,768]^T; out = relu(.)·W3 + ...
// 256 CTAs (M=64 each), 256 thr (8 warps, 4M x 2N, warp 16x64), 2 CTAs/SM.
// ---------------------------------------------------------------------------
#define TAIL_STAGE 24576                      // 8KB A + 16KB B
#define SMEM_TAIL  (3 * TAIL_STAGE)           // 72 KB

static __device__ __forceinline__ void issue_tail(uint32_t sb, int ic, int st,
                                                  int m0, int t)
{
    int seg = ic >> 2;
    int kc  = (ic & 3) * 64;
    const __nv_bfloat16 *Ap, *Bp;
    if (seg == 0)      { Ap = g_Hhi;   Bp = g_W2thi; }
    else if (seg == 1) { Ap = g_Hlo;   Bp = g_W2thi; }
    else               { Ap = g_Hhi;   Bp = g_W2tlo; }
    uint32_t ab = sb + st * TAIL_STAGE;
    uint32_t bb = ab + 8192;
    #pragma unroll
    for (int l = 0; l < 2; l++) {             // A: 64 rows x 128B
        int f = t + l * 256;
        int row = f >> 3, kq = (f & 7) * 8;
        cp16(ab + SWZ(row * 128 + kq * 2), Ap + (size_t)(m0 + row) * H1D + kc + kq);
    }
    #pragma unroll
    for (int l = 0; l < 4; l++) {             // B: 128 rows x 128B
        int f = t + l * 256;
        int row = f >> 3, kq = (f & 7) * 8;
        cp16(bb + SWZ(row * 128 + kq * 2), Bp + (size_t)row * H1D + kc + kq);
    }
}

__global__ __launch_bounds__(256, 2) void k_mma_tail(
    const float* __restrict__ b2, const float* __restrict__ W3,
    const float* __restrict__ b3, float* __restrict__ out)
{
    extern __shared__ char smem[];
    __shared__ float b2s[128];
    __shared__ float w3s[128];
    __shared__ float ps[64][2];
    uint32_t sb = smem_u32(smem);
    int t = threadIdx.x;
    int lane = t & 31, wid = t >> 5;
    int wm = wid & 3, wn = wid >> 2;          // 4M x 2N warps, warp tile 16x64
    int m0 = blockIdx.x * 64;

    if (t < 128) { b2s[t] = b2[t]; w3s[t] = W3[t]; }

    float c[8][4];
    #pragma unroll
    for (int j = 0; j < 8; j++)
        #pragma unroll
        for (int q = 0; q < 4; q++) c[j][q] = 0.f;

    const int NC = 12;
    issue_tail(sb, 0, 0, m0, t); CP_COMMIT();
    issue_tail(sb, 1, 1, m0, t); CP_COMMIT();

    int a_row  = (lane & 15);
    int a_koff = (lane >> 4) * 16;
    int b_row  = ((lane >> 4) & 1) * 8 + (lane & 7);
    int b_koff = ((lane >> 3) & 1) * 16;

    #pragma unroll 1
    for (int ic = 0; ic < NC; ic++) {
        __syncthreads();
        if (ic + 2 < NC) issue_tail(sb, ic + 2, (ic + 2) % 3, m0, t);
        CP_COMMIT();
        CP_WAIT2();
        __syncthreads();

        uint32_t ab = sb + (ic % 3) * TAIL_STAGE;
        uint32_t bb = ab + 8192;
        #pragma unroll
        for (int ks = 0; ks < 4; ks++) {
            uint32_t a[4], b[8][2];
            LDSM4(a[0], a[1], a[2], a[3],
                  ab + SWZ((wm * 16 + a_row) * 128 + ks * 32 + a_koff));
            #pragma unroll
            for (int jp = 0; jp < 4; jp++)
                LDSM4(b[2 * jp][0], b[2 * jp][1], b[2 * jp + 1][0], b[2 * jp + 1][1],
                      bb + SWZ((wn * 64 + jp * 16 + b_row) * 128 + ks * 32 + b_koff));
            #pragma unroll
            for (int j = 0; j < 8; j++)
                MMA16816(c[j], a, b[j]);
        }
    }

    // Epilogue: relu(c + b2) dot W3 over this warp's 64 cols, lane-reduce,
    // then cross-warp (wn) reduce via smem.
    float p0 = 0.f, p1 = 0.f;
    #pragma unroll
    for (int j = 0; j < 8; j++) {
        int n = wn * 64 + j * 8 + (lane & 3) * 2;
        p0 += fmaxf(c[j][0] + b2s[n],     0.f) * w3s[n];
        p0 += fmaxf(c[j][1] + b2s[n + 1], 0.f) * w3s[n + 1];
        p1 += fmaxf(c[j][2] + b2s[n],     0.f) * w3s[n];
        p1 += fmaxf(c[j][3] + b2s[n + 1], 0.f) * w3s[n + 1];
    }
    p0 += __shfl_xor_sync(0xFFFFFFFF, p0, 1);
    p0 += __shfl_xor_sync(0xFFFFFFFF, p0, 2);
    p1 += __shfl_xor_sync(0xFFFFFFFF, p1, 1);
    p1 += __shfl_xor_sync(0xFFFFFFFF, p1, 2);
    if ((lane & 3) == 0) {
        ps[wm * 16 + (lane >> 2)][wn]     = p0;
        ps[wm * 16 + (lane >> 2) + 8][wn] = p1;
    }
    __syncthreads();

    if (t < 64) {
        int m = m0 + t;
        float s = b3[0] + g_ADD[m] + ps[t][0] + ps[t][1];
        #pragma unroll
        for (int i = 0; i < 16; i++) s += g_MS[m * 16 + i] * g_US[m * 16 + i];
        out[m] = s;
    }
}

// ---------------------------------------------------------------------------
extern "C" void kernel_launch(void* const* d_in, const int* in_sizes, int n_in,
                              void* d_out, int out_size)
{
    const float* mv = (const float*)d_in[0];
    const float* uv = (const float*)d_in[1];
    const float* Wm = (const float*)d_in[2];
    const float* bm = (const float*)d_in[3];
    const float* Wu = (const float*)d_in[4];
    const float* bu = (const float*)d_in[5];
    const float* W1 = (const float*)d_in[6];
    const float* b1 = (const float*)d_in[7];
    const float* W2 = (const float*)d_in[8];
    const float* b2 = (const float*)d_in[9];
    const float* W3 = (const float*)d_in[10];
    const float* b3 = (const float*)d_in[11];
    float* out = (float*)d_out;

    cudaFuncSetAttribute(k_mma_main, cudaFuncAttributeMaxDynamicSharedMemorySize, SMEM_MAIN);
    cudaFuncSetAttribute(k_mma_tail, cudaFuncAttributeMaxDynamicSharedMemorySize, SMEM_TAIL);

    // Merged precompute: 64 combine blocks + 194 small blocks, one wave.
    const int PRE_BLKS = 64 + (KD * 16 + NOUT + H2D * H1D + 255) / 256;
    k_pre<<<PRE_BLKS, 256>>>(Wm, bm, Wu, bu, W1, b1, W2);

    // Main tensor-core GEMM, one wave of 128 CTAs, A/Bhi fragment reuse.
    k_mma_main<<<BATCH / 128, 512, SMEM_MAIN>>>(mv, uv);

    // Tail tensor-core GEMM + final reduction, 256 CTAs, 2/SM.
    k_mma_tail<<<BATCH / 64, 256, SMEM_TAIL>>>(b2, W3, b3, out);
}

// round 10
// speedup vs baseline: 1.3087x; 1.0627x over previous
#include <cuda_runtime.h>
#include <cuda_bf16.h>
#include <cstdint>

#define BATCH 16384
#define KD    1024
#define NOUT  289
#define H1D   256
#define H2D   128

// ---------------------------------------------------------------------------
// Device scratch (zero-initialized at load; Bt pad rows 289..319 stay 0).
// ---------------------------------------------------------------------------
__device__ float         g_cbias[NOUT];
__device__ __nv_bfloat16 g_Bthi[320 * KD];
__device__ __nv_bfloat16 g_Btlo[320 * KD];
__device__ __nv_bfloat16 g_Hhi[BATCH * H1D];
__device__ __nv_bfloat16 g_Hlo[BATCH * H1D];
__device__ __nv_bfloat16 g_W2thi[H2D * H1D];
__device__ __nv_bfloat16 g_W2tlo[H2D * H1D];
__device__ float         g_MS[BATCH * 16];
__device__ float         g_US[BATCH * 16];
__device__ float         g_ADD[BATCH];

// ---------------------------------------------------------------------------
// Helpers (base sm_103 PTX only: mma.sync / ldmatrix / cp.async)
// ---------------------------------------------------------------------------
static __device__ __forceinline__ uint32_t smem_u32(const void* p) {
    uint32_t a;
    asm("{ .reg .u64 t; cvta.to.shared.u64 t, %1; cvt.u32.u64 %0, t; }" : "=r"(a) : "l"(p));
    return a;
}
static __device__ __forceinline__ void cp16(uint32_t dst, const void* src) {
    asm volatile("cp.async.cg.shared.global [%0], [%1], 16;\n" :: "r"(dst), "l"(src));
}
#define CP_COMMIT() asm volatile("cp.async.commit_group;\n" ::: "memory")
#define CP_WAIT0()  asm volatile("cp.async.wait_group 0;\n" ::: "memory")
#define CP_WAIT2()  asm volatile("cp.async.wait_group 2;\n" ::: "memory")

#define LDSM4(r0, r1, r2, r3, addr) \
    asm volatile("ldmatrix.sync.aligned.m8n8.x4.shared.b16 {%0,%1,%2,%3}, [%4];" \
                 : "=r"(r0), "=r"(r1), "=r"(r2), "=r"(r3) : "r"(addr))

#define MMA16816(c, a, b) \
    asm volatile("mma.sync.aligned.m16n8k16.row.col.f32.bf16.bf16.f32 " \
                 "{%0,%1,%2,%3},{%4,%5,%6,%7},{%8,%9},{%0,%1,%2,%3};" \
                 : "+f"((c)[0]), "+f"((c)[1]), "+f"((c)[2]), "+f"((c)[3]) \
                 : "r"((a)[0]), "r"((a)[1]), "r"((a)[2]), "r"((a)[3]), \
                   "r"((b)[0]), "r"((b)[1]))

#define SWZ(x)   ((x) ^ (((x) >> 3) & 0x70))   // 128B-row swizzle

static __device__ __forceinline__ void split2(float v, __nv_bfloat16& h, __nv_bfloat16& l) {
    h = __float2bfloat16(v);
    l = __float2bfloat16(v - __bfloat162float(h));
}
static __device__ __forceinline__ uint32_t pack_bf2(__nv_bfloat16 a, __nv_bfloat16 b) {
    __nv_bfloat162 p; p.x = a; p.y = b;
    return *reinterpret_cast<uint32_t*>(&p);
}

// ---------------------------------------------------------------------------
// K0: merged precompute.
//   blocks [0,128):   combine GEMM, 32x64 tiles -> Bt(hi/lo) transposed+split
//   blocks [128,136): cbias[0:256] via 8-way j-split + shfl reduce
//   blocks [136,329): ms/us/add rows of Bt, cbias[256:289], W2t split
// ---------------------------------------------------------------------------
__global__ __launch_bounds__(256) void k_pre(
    const float* __restrict__ Wm, const float* __restrict__ bm,
    const float* __restrict__ Wu, const float* __restrict__ bu,
    const float* __restrict__ W1, const float* __restrict__ b1,
    const float* __restrict__ W2)
{
    __shared__ float As[16][32];
    __shared__ float Bs[16][64];
    int bid = blockIdx.x;
    int tid = threadIdx.x;

    if (bid < 128) {
        // ---- combine GEMM: Bt[n, kglob] = (Wm|Wu)[kglob, :256] @ W1half ----
        int z   = bid >> 6;                   // tower
        int rem = bid & 63;                   // 16 mblk x 4 nblk
        const float* A  = (z == 0) ? Wm : Wu;
        const float* Bw = (z == 0) ? W1 : (W1 + 256 * 256);
        int koff        = (z == 0) ? 0  : 512;
        const int lda = 257, ldb = 256, K = 256;

        int m0 = (rem >> 2) * 32, n0 = (rem & 3) * 64;
        int tx = tid & 15, ty = tid >> 4;
        float acc[2][4] = {};

        for (int k0 = 0; k0 < K; k0 += 16) {
            {   // As: 32 m-rows x 16 k, 2 scalars per thread, stored [k][m]
                int m = tid & 31;
                int kq = (tid >> 5) * 2;
                const float* ap = A + (m0 + m) * lda + k0 + kq;
                As[kq][m] = ap[0];
                As[kq + 1][m] = ap[1];
            }
            {   // Bs: 16 k x 64 n, float4
                int kr = tid >> 4;
                int nq = (tid & 15) * 4;
                float4 v = *reinterpret_cast<const float4*>(Bw + (k0 + kr) * ldb + n0 + nq);
                *reinterpret_cast<float4*>(&Bs[kr][nq]) = v;
            }
            __syncthreads();
            #pragma unroll
            for (int kk = 0; kk < 16; kk++) {
                float a[2], b[4];
                #pragma unroll
                for (int i = 0; i < 2; i++) a[i] = As[kk][ty * 2 + i];
                #pragma unroll
                for (int j = 0; j < 4; j++) b[j] = Bs[kk][tx * 4 + j];
                #pragma unroll
                for (int i = 0; i < 2; i++)
                    #pragma unroll
                    for (int j = 0; j < 4; j++) acc[i][j] += a[i] * b[j];
            }
            __syncthreads();
        }
        #pragma unroll
        for (int i = 0; i < 2; i++)
            #pragma unroll
            for (int j = 0; j < 4; j++) {
                int kg = koff + m0 + ty * 2 + i;
                int nr = n0 + tx * 4 + j;
                __nv_bfloat16 h, l;
                split2(acc[i][j], h, l);
                g_Bthi[(size_t)nr * KD + kg] = h;
                g_Btlo[(size_t)nr * KD + kg] = l;
            }
        return;
    }

    if (bid < 136) {
        // ---- cbias[c] = b1[c] + sum_j (bm|bu)[j] * W1[j*256+c], 8-way split
        int cg = tid >> 3, jp = tid & 7;
        int c = (bid - 128) * 32 + cg;
        float p = 0.f;
        int j0 = jp * 64;
        #pragma unroll 4
        for (int i = 0; i < 64; i++) {
            int j = j0 + i;
            float bv = (j < 256) ? bm[j] : bu[j - 256];
            p += bv * W1[j * 256 + c];
        }
        p += __shfl_down_sync(0xFFFFFFFFu, p, 4, 8);
        p += __shfl_down_sync(0xFFFFFFFFu, p, 2, 8);
        p += __shfl_down_sync(0xFFFFFFFFu, p, 1, 8);
        if (jp == 0) g_cbias[c] = b1[c] + p;
        return;
    }

    // ---- rest ----
    int t = (bid - 136) * 256 + tid;
    if (t < KD * 16) {
        int k = t >> 4, d = t & 15;
        float s = 0.f;
        __nv_bfloat16 h, l;
        if (k < 512) {
            #pragma unroll
            for (int i = 0; i < 16; i++) s += Wm[k * 257 + i * 16 + d];
            split2(s, h, l);
            g_Bthi[(size_t)(256 + d) * KD + k] = h;
            g_Btlo[(size_t)(256 + d) * KD + k] = l;
            if (d == 0) {
                split2(Wm[k * 257 + 256], h, l);
                g_Bthi[(size_t)288 * KD + k] = h;
                g_Btlo[(size_t)288 * KD + k] = l;
            }
        } else {
            int ku = k - 512;
            #pragma unroll
            for (int i = 0; i < 16; i++) s += Wu[ku * 257 + i * 16 + d];
            split2(s, h, l);
            g_Bthi[(size_t)(272 + d) * KD + k] = h;
            g_Btlo[(size_t)(272 + d) * KD + k] = l;
            if (d == 0) {
                split2(Wu[ku * 257 + 256], h, l);
                g_Bthi[(size_t)288 * KD + k] = h;
                g_Btlo[(size_t)288 * KD + k] = l;
            }
        }
        return;
    }
    int c = t - KD * 16;
    if (c < 33) {
        int cc = 256 + c;
        float v;
        if (cc < 272) {
            int d = cc - 256; v = 0.f;
            #pragma unroll
            for (int i = 0; i < 16; i++) v += bm[i * 16 + d];
        } else if (cc < 288) {
            int d = cc - 272; v = 0.f;
            #pragma unroll
            for (int i = 0; i < 16; i++) v += bu[i * 16 + d];
        } else {
            v = bm[256] + bu[256];
        }
        g_cbias[cc] = v;
        return;
    }
    int j = c - 33;
    if (j < H2D * H1D) {
        int r = j >> 8, cc = j & 255;        // W2t[r][cc] = W2[cc][r]
        __nv_bfloat16 h, l;
        split2(W2[cc * H2D + r], h, l);
        g_W2thi[j] = h; g_W2tlo[j] = l;
    }
}

// ---------------------------------------------------------------------------
// K1: main mma.sync GEMM with fused fp32->bf16 hi/lo split of A.
// C[16384, 320] = A[16384,1024 fp32] (x) Bt(hi/lo)[320,1024]^T, 3 split terms.
// 128 CTAs (one wave), 512 thr (16 warps, 4M x 4N, warp 32x80), K-chunk=64,
// 2-stage double buffer (112KB/stage). 16 syncs total; A/Bhi fragments reused.
// ---------------------------------------------------------------------------
#define CK         64
#define NCHUNK     16
#define AHI_OFF    0
#define ALO_OFF    16384
#define BHI_OFF    32768
#define BLO_OFF    73728
#define MAIN_STAGE 114688                     // 16+16+40+40 KB
#define SMEM_MAIN  (2 * MAIN_STAGE)           // 224 KB

static __device__ __forceinline__ void ldg_a(float4* p, int ch, int m0, int t,
                                             const float* __restrict__ mv,
                                             const float* __restrict__ uv)
{
    int kc = ch * CK;
    const float* base = (kc < 512) ? (mv + kc) : (uv + kc - 512);
    #pragma unroll
    for (int l = 0; l < 4; l++) {
        int f = t + l * 512;
        int row = f >> 4, q = f & 15;
        p[l] = *reinterpret_cast<const float4*>(base + (size_t)(m0 + row) * 512 + q * 4);
    }
}

static __device__ __forceinline__ void sts_a(const float4* p, uint32_t stg, int t)
{
    #pragma unroll
    for (int l = 0; l < 4; l++) {
        int f = t + l * 512;
        int row = f >> 4, q = f & 15;
        __nv_bfloat16 h0, l0, h1, l1, h2, l2, h3, l3;
        split2(p[l].x, h0, l0); split2(p[l].y, h1, l1);
        split2(p[l].z, h2, l2); split2(p[l].w, h3, l3);
        uint32_t hi0 = pack_bf2(h0, h1), hi1 = pack_bf2(h2, h3);
        uint32_t lo0 = pack_bf2(l0, l1), lo1 = pack_bf2(l2, l3);
        uint32_t off = SWZ(row * 128 + q * 8);
        asm volatile("st.shared.v2.b32 [%0], {%1,%2};"
                     :: "r"(stg + AHI_OFF + off), "r"(hi0), "r"(hi1) : "memory");
        asm volatile("st.shared.v2.b32 [%0], {%1,%2};"
                     :: "r"(stg + ALO_OFF + off), "r"(lo0), "r"(lo1) : "memory");
    }
}

static __device__ __forceinline__ void cp_b(uint32_t stg, int ch, int t)
{
    int kc = ch * CK;
    #pragma unroll
    for (int l = 0; l < 10; l++) {
        int f = t + l * 512;                  // 0..5119: 2560 hi + 2560 lo units
        int lobuf = f >= 2560;
        int fr = lobuf ? f - 2560 : f;
        int row = fr >> 3, u = fr & 7;
        const __nv_bfloat16* src = (lobuf ? g_Btlo : g_Bthi) + (size_t)row * KD + kc + u * 8;
        cp16(stg + (lobuf ? BLO_OFF : BHI_OFF) + SWZ(row * 128 + u * 16), src);
    }
}

static __device__ __forceinline__ void chunk_ks(uint32_t stg, int ks,
                                                int wm, int wn,
                                                int a_row, int a_koff,
                                                int b_row, int b_koff,
                                                float c[2][10][4])
{
    uint32_t ahi[2][4], alo[2][4];
    #pragma unroll
    for (int mt = 0; mt < 2; mt++) {
        uint32_t ra = SWZ((wm * 32 + mt * 16 + a_row) * 128 + ks * 32 + a_koff);
        LDSM4(ahi[mt][0], ahi[mt][1], ahi[mt][2], ahi[mt][3], stg + AHI_OFF + ra);
        LDSM4(alo[mt][0], alo[mt][1], alo[mt][2], alo[mt][3], stg + ALO_OFF + ra);
    }
    #pragma unroll
    for (int jp = 0; jp < 5; jp++) {
        uint32_t rb = SWZ((wn * 80 + jp * 16 + b_row) * 128 + ks * 32 + b_koff);
        uint32_t b0[2], b1[2];
        LDSM4(b0[0], b0[1], b1[0], b1[1], stg + BHI_OFF + rb);   // Bhi
        #pragma unroll
        for (int mt = 0; mt < 2; mt++) {
            MMA16816(c[mt][2 * jp],     ahi[mt], b0);
            MMA16816(c[mt][2 * jp + 1], ahi[mt], b1);
            MMA16816(c[mt][2 * jp],     alo[mt], b0);
            MMA16816(c[mt][2 * jp + 1], alo[mt], b1);
        }
        LDSM4(b0[0], b0[1], b1[0], b1[1], stg + BLO_OFF + rb);   // Blo
        #pragma unroll
        for (int mt = 0; mt < 2; mt++) {
            MMA16816(c[mt][2 * jp],     ahi[mt], b0);
            MMA16816(c[mt][2 * jp + 1], ahi[mt], b1);
        }
    }
}

__global__ __launch_bounds__(512, 1) void k_mma_main(
    const float* __restrict__ mv, const float* __restrict__ uv)
{
    extern __shared__ char smem[];
    uint32_t sb = smem_u32(smem);
    int t = threadIdx.x;
    int lane = t & 31, wid = t >> 5;
    int wm = wid & 3, wn = wid >> 2;          // 4M x 4N warps
    int m0 = blockIdx.x * 128;

    float c[2][10][4];
    #pragma unroll
    for (int i = 0; i < 2; i++)
        #pragma unroll
        for (int j = 0; j < 10; j++)
            #pragma unroll
            for (int q = 0; q < 4; q++) c[i][j][q] = 0.f;

    int a_row  = (lane & 15);
    int a_koff = (lane >> 4) * 16;
    int b_row  = ((lane >> 4) & 1) * 8 + (lane & 7);
    int b_koff = ((lane >> 3) & 1) * 16;

    // Prologue: chunk 0.
    {
        float4 q0[4];
        ldg_a(q0, 0, m0, t, mv, uv);
        cp_b(sb, 0, t); CP_COMMIT();
        sts_a(q0, sb, t);
    }

    float4 pf[4];
    #pragma unroll 1
    for (int ic = 0; ic < NCHUNK; ic++) {
        bool pfv = (ic + 1 < NCHUNK);
        if (pfv) ldg_a(pf, ic + 1, m0, t, mv, uv);   // LDG issued a chunk ahead
        CP_WAIT0();                                   // B(ic) arrived
        __syncthreads();                              // compute(ic-1) done -> other stage free
        uint32_t nstg = sb + ((ic + 1) & 1) * MAIN_STAGE;
        if (pfv) cp_b(nstg, ic + 1, t);
        CP_COMMIT();

        uint32_t stg = sb + (ic & 1) * MAIN_STAGE;
        chunk_ks(stg, 0, wm, wn, a_row, a_koff, b_row, b_koff, c);
        chunk_ks(stg, 1, wm, wn, a_row, a_koff, b_row, b_koff, c);
        if (pfv) sts_a(pf, nstg, t);                  // A(ic+1): LDG latency hidden by ks 0-1
        chunk_ks(stg, 2, wm, wn, a_row, a_koff, b_row, b_koff, c);
        chunk_ks(stg, 3, wm, wn, a_row, a_koff, b_row, b_koff, c);
    }

    // Epilogue: bias, relu, split / route.
    #pragma unroll
    for (int mt = 0; mt < 2; mt++) {
        int rbase = m0 + wm * 32 + mt * 16 + (lane >> 2);
        #pragma unroll
        for (int half = 0; half < 2; half++) {
            int m = rbase + half * 8;
            #pragma unroll
            for (int j = 0; j < 10; j++) {
                int n = wn * 80 + j * 8 + (lane & 3) * 2;
                float v0 = c[mt][j][half * 2 + 0] + g_cbias[n < NOUT ? n : 0];
                float v1 = c[mt][j][half * 2 + 1] + g_cbias[(n + 1) < NOUT ? (n + 1) : 0];
                if (n < 256) {
                    v0 = fmaxf(v0, 0.f); v1 = fmaxf(v1, 0.f);
                    __nv_bfloat16 h0, l0, h1, l1;
                    split2(v0, h0, l0); split2(v1, h1, l1);
                    *reinterpret_cast<uint32_t*>(&g_Hhi[(size_t)m * H1D + n]) = pack_bf2(h0, h1);
                    *reinterpret_cast<uint32_t*>(&g_Hlo[(size_t)m * H1D + n]) = pack_bf2(l0, l1);
                } else {
                    #pragma unroll
                    for (int e = 0; e < 2; e++) {
                        int ne = n + e;
                        float ve = e ? v1 : v0;
                        if (ne < 272)       g_MS[m * 16 + ne - 256] = ve;
                        else if (ne < 288)  g_US[m * 16 + ne - 272] = ve;
                        else if (ne == 288) g_ADD[m] = ve;
                    }
                }
            }
        }
    }
}

// ---------------------------------------------------------------------------
// K2: tail mma.sync GEMM + final reduce, re-tiled for occupancy.
// C[16384,128] = Hcat[16384,768] @ W2tcat[128,768]^T; out = relu(.)·W3 + ...
// 256 CTAs (M=64 each), 256 thr (8 warps, 4M x 2N, warp 16x64), 2 CTAs/SM.
// ---------------------------------------------------------------------------
#define TAIL_STAGE 24576                      // 8KB A + 16KB B
#define SMEM_TAIL  (3 * TAIL_STAGE)           // 72 KB

static __device__ __forceinline__ void issue_tail(uint32_t sb, int ic, int st,
                                                  int m0, int t)
{
    int seg = ic >> 2;
    int kc  = (ic & 3) * 64;
    const __nv_bfloat16 *Ap, *Bp;
    if (seg == 0)      { Ap = g_Hhi;   Bp = g_W2thi; }
    else if (seg == 1) { Ap = g_Hlo;   Bp = g_W2thi; }
    else               { Ap = g_Hhi;   Bp = g_W2tlo; }
    uint32_t ab = sb + st * TAIL_STAGE;
    uint32_t bb = ab + 8192;
    #pragma unroll
    for (int l = 0; l < 2; l++) {             // A: 64 rows x 128B
        int f = t + l * 256;
        int row = f >> 3, kq = (f & 7) * 8;
        cp16(ab + SWZ(row * 128 + kq * 2), Ap + (size_t)(m0 + row) * H1D + kc + kq);
    }
    #pragma unroll
    for (int l = 0; l < 4; l++) {             // B: 128 rows x 128B
        int f = t + l * 256;
        int row = f >> 3, kq = (f & 7) * 8;
        cp16(bb + SWZ(row * 128 + kq * 2), Bp + (size_t)row * H1D + kc + kq);
    }
}

__global__ __launch_bounds__(256, 2) void k_mma_tail(
    const float* __restrict__ b2, const float* __restrict__ W3,
    const float* __restrict__ b3, float* __restrict__ out)
{
    extern __shared__ char smem[];
    __shared__ float b2s[128];
    __shared__ float w3s[128];
    __shared__ float ps[64][2];
    uint32_t sb = smem_u32(smem);
    int t = threadIdx.x;
    int lane = t & 31, wid = t >> 5;
    int wm = wid & 3, wn = wid >> 2;          // 4M x 2N warps, warp tile 16x64
    int m0 = blockIdx.x * 64;

    if (t < 128) { b2s[t] = b2[t]; w3s[t] = W3[t]; }

    float c[8][4];
    #pragma unroll
    for (int j = 0; j < 8; j++)
        #pragma unroll
        for (int q = 0; q < 4; q++) c[j][q] = 0.f;

    const int NC = 12;
    issue_tail(sb, 0, 0, m0, t); CP_COMMIT();
    issue_tail(sb, 1, 1, m0, t); CP_COMMIT();

    int a_row  = (lane & 15);
    int a_koff = (lane >> 4) * 16;
    int b_row  = ((lane >> 4) & 1) * 8 + (lane & 7);
    int b_koff = ((lane >> 3) & 1) * 16;

    #pragma unroll 1
    for (int ic = 0; ic < NC; ic++) {
        __syncthreads();
        if (ic + 2 < NC) issue_tail(sb, ic + 2, (ic + 2) % 3, m0, t);
        CP_COMMIT();
        CP_WAIT2();
        __syncthreads();

        uint32_t ab = sb + (ic % 3) * TAIL_STAGE;
        uint32_t bb = ab + 8192;
        #pragma unroll
        for (int ks = 0; ks < 4; ks++) {
            uint32_t a[4], b[8][2];
            LDSM4(a[0], a[1], a[2], a[3],
                  ab + SWZ((wm * 16 + a_row) * 128 + ks * 32 + a_koff));
            #pragma unroll
            for (int jp = 0; jp < 4; jp++)
                LDSM4(b[2 * jp][0], b[2 * jp][1], b[2 * jp + 1][0], b[2 * jp + 1][1],
                      bb + SWZ((wn * 64 + jp * 16 + b_row) * 128 + ks * 32 + b_koff));
            #pragma unroll
            for (int j = 0; j < 8; j++)
                MMA16816(c[j], a, b[j]);
        }
    }

    // Epilogue: relu(c + b2) dot W3 over this warp's 64 cols, lane-reduce,
    // then cross-warp (wn) reduce via smem.
    float p0 = 0.f, p1 = 0.f;
    #pragma unroll
    for (int j = 0; j < 8; j++) {
        int n = wn * 64 + j * 8 + (lane & 3) * 2;
        p0 += fmaxf(c[j][0] + b2s[n],     0.f) * w3s[n];
        p0 += fmaxf(c[j][1] + b2s[n + 1], 0.f) * w3s[n + 1];
        p1 += fmaxf(c[j][2] + b2s[n],     0.f) * w3s[n];
        p1 += fmaxf(c[j][3] + b2s[n + 1], 0.f) * w3s[n + 1];
    }
    p0 += __shfl_xor_sync(0xFFFFFFFF, p0, 1);
    p0 += __shfl_xor_sync(0xFFFFFFFF, p0, 2);
    p1 += __shfl_xor_sync(0xFFFFFFFF, p1, 1);
    p1 += __shfl_xor_sync(0xFFFFFFFF, p1, 2);
    if ((lane & 3) == 0) {
        ps[wm * 16 + (lane >> 2)][wn]     = p0;
        ps[wm * 16 + (lane >> 2) + 8][wn] = p1;
    }
    __syncthreads();

    if (t < 64) {
        int m = m0 + t;
        float s = b3[0] + g_ADD[m] + ps[t][0] + ps[t][1];
        #pragma unroll
        for (int i = 0; i < 16; i++) s += g_MS[m * 16 + i] * g_US[m * 16 + i];
        out[m] = s;
    }
}

// ---------------------------------------------------------------------------
extern "C" void kernel_launch(void* const* d_in, const int* in_sizes, int n_in,
                              void* d_out, int out_size)
{
    const float* mv = (const float*)d_in[0];
    const float* uv = (const float*)d_in[1];
    const float* Wm = (const float*)d_in[2];
    const float* bm = (const float*)d_in[3];
    const float* Wu = (const float*)d_in[4];
    const float* bu = (const float*)d_in[5];
    const float* W1 = (const float*)d_in[6];
    const float* b1 = (const float*)d_in[7];
    const float* W2 = (const float*)d_in[8];
    const float* b2 = (const float*)d_in[9];
    const float* W3 = (const float*)d_in[10];
    const float* b3 = (const float*)d_in[11];
    float* out = (float*)d_out;

    cudaFuncSetAttribute(k_mma_main, cudaFuncAttributeMaxDynamicSharedMemorySize, SMEM_MAIN);
    cudaFuncSetAttribute(k_mma_tail, cudaFuncAttributeMaxDynamicSharedMemorySize, SMEM_TAIL);

    // Merged precompute: 128 combine + 8 bias + 193 rest blocks.
    const int PRE_BLKS = 136 + (KD * 16 + 33 + H2D * H1D + 255) / 256;
    k_pre<<<PRE_BLKS, 256>>>(Wm, bm, Wu, bu, W1, b1, W2);

    // Main tensor-core GEMM, one wave of 128 CTAs, 2-stage CK=64 pipeline.
    k_mma_main<<<BATCH / 128, 512, SMEM_MAIN>>>(mv, uv);

    // Tail tensor-core GEMM + final reduction, 256 CTAs, 2/SM.
    k_mma_tail<<<BATCH / 64, 256, SMEM_TAIL>>>(b2, W3, b3, out);
}

// round 12
// speedup vs baseline: 1.3243x; 1.0119x over previous
#include <cuda_runtime.h>
#include <cuda_bf16.h>
#include <cstdint>

#define BATCH 16384
#define KD    1024
#define NOUT  289
#define H1D   256
#define H2D   128

// ---------------------------------------------------------------------------
// Device scratch (zero-initialized at load; Bt pad rows 289..319 stay 0).
// ---------------------------------------------------------------------------
__device__ float         g_cbias[NOUT];
__device__ __nv_bfloat16 g_Bthi[320 * KD];
__device__ __nv_bfloat16 g_Btlo[320 * KD];
__device__ __nv_bfloat16 g_Hhi[BATCH * H1D];
__device__ __nv_bfloat16 g_Hlo[BATCH * H1D];
__device__ __nv_bfloat16 g_W2thi[H2D * H1D];
__device__ __nv_bfloat16 g_W2tlo[H2D * H1D];
__device__ float         g_MS[BATCH * 16];
__device__ float         g_US[BATCH * 16];
__device__ float         g_ADD[BATCH];

// ---------------------------------------------------------------------------
// Helpers (base sm_103 PTX only: mma.sync / ldmatrix / cp.async)
// ---------------------------------------------------------------------------
static __device__ __forceinline__ uint32_t smem_u32(const void* p) {
    uint32_t a;
    asm("{ .reg .u64 t; cvta.to.shared.u64 t, %1; cvt.u32.u64 %0, t; }" : "=r"(a) : "l"(p));
    return a;
}
static __device__ __forceinline__ void cp16(uint32_t dst, const void* src) {
    asm volatile("cp.async.cg.shared.global [%0], [%1], 16;\n" :: "r"(dst), "l"(src));
}
#define CP_COMMIT() asm volatile("cp.async.commit_group;\n" ::: "memory")
#define CP_WAIT0()  asm volatile("cp.async.wait_group 0;\n" ::: "memory")
#define CP_WAIT2()  asm volatile("cp.async.wait_group 2;\n" ::: "memory")

#define LDSM4(r0, r1, r2, r3, addr) \
    asm volatile("ldmatrix.sync.aligned.m8n8.x4.shared.b16 {%0,%1,%2,%3}, [%4];" \
                 : "=r"(r0), "=r"(r1), "=r"(r2), "=r"(r3) : "r"(addr))

#define MMA16816(c, a, b) \
    asm volatile("mma.sync.aligned.m16n8k16.row.col.f32.bf16.bf16.f32 " \
                 "{%0,%1,%2,%3},{%4,%5,%6,%7},{%8,%9},{%0,%1,%2,%3};" \
                 : "+f"((c)[0]), "+f"((c)[1]), "+f"((c)[2]), "+f"((c)[3]) \
                 : "r"((a)[0]), "r"((a)[1]), "r"((a)[2]), "r"((a)[3]), \
                   "r"((b)[0]), "r"((b)[1]))

#define SWZ(x)   ((x) ^ (((x) >> 3) & 0x70))   // 128B-row swizzle

static __device__ __forceinline__ void split2(float v, __nv_bfloat16& h, __nv_bfloat16& l) {
    h = __float2bfloat16(v);
    l = __float2bfloat16(v - __bfloat162float(h));
}
static __device__ __forceinline__ uint32_t pack_bf2(__nv_bfloat16 a, __nv_bfloat16 b) {
    __nv_bfloat162 p; p.x = a; p.y = b;
    return *reinterpret_cast<uint32_t*>(&p);
}

// ---------------------------------------------------------------------------
// K0: merged precompute.
//   blocks [0,128):   combine GEMM, 32x64 tile, FULL-K smem strips, ONE sync
//   blocks [128,136): cbias[0:256] via 8-way j-split + shfl reduce
//   blocks [136,...): ms/us/add rows of Bt, cbias[256:289], W2t split
// ---------------------------------------------------------------------------
#define PRE_SMEM ((256 * 33 + 256 * 64) * 4)   // 99328 bytes

__global__ __launch_bounds__(256) void k_pre(
    const float* __restrict__ Wm, const float* __restrict__ bm,
    const float* __restrict__ Wu, const float* __restrict__ bu,
    const float* __restrict__ W1, const float* __restrict__ b1,
    const float* __restrict__ W2)
{
    extern __shared__ float dsm[];
    int bid = blockIdx.x;
    int tid = threadIdx.x;

    if (bid < 128) {
        // ---- combine GEMM: Bt[n, kglob] = (Wm|Wu)[kglob, :256] @ W1half ----
        int z   = bid >> 6;                   // tower
        int rem = bid & 63;                   // 16 mblk x 4 nblk
        const float* A  = (z == 0) ? Wm : Wu;
        const float* Bw = (z == 0) ? W1 : (W1 + 256 * 256);
        int koff        = (z == 0) ? 0  : 512;
        const int lda = 257, ldb = 256;

        int m0 = (rem >> 2) * 32, n0 = (rem & 3) * 64;
        float* As = dsm;                      // [256 k][33 m-pad]
        float* Bs = dsm + 256 * 33;           // [256 k][64 n]

        // A strip: 32 rows x 256 k, coalesced per row; store k-major.
        #pragma unroll 4
        for (int r = 0; r < 32; r++)
            As[tid * 33 + r] = A[(m0 + r) * lda + tid];
        // B strip: 256 k x 64 n, float4 coalesced.
        #pragma unroll
        for (int i = 0; i < 16; i++) {
            int f = i * 256 + tid;
            int k = f >> 4, nq = (f & 15) * 4;
            float4 v = *reinterpret_cast<const float4*>(Bw + k * ldb + n0 + nq);
            *reinterpret_cast<float4*>(&Bs[k * 64 + nq]) = v;
        }
        __syncthreads();                      // the ONLY barrier

        int tx = tid & 15, ty = tid >> 4;     // m = ty*2+i, n = tx*4+j
        float acc[2][4] = {};
        #pragma unroll 8
        for (int k = 0; k < 256; k++) {
            float a0 = As[k * 33 + ty * 2];
            float a1 = As[k * 33 + ty * 2 + 1];
            float4 b = *reinterpret_cast<const float4*>(&Bs[k * 64 + tx * 4]);
            acc[0][0] += a0 * b.x; acc[0][1] += a0 * b.y;
            acc[0][2] += a0 * b.z; acc[0][3] += a0 * b.w;
            acc[1][0] += a1 * b.x; acc[1][1] += a1 * b.y;
            acc[1][2] += a1 * b.z; acc[1][3] += a1 * b.w;
        }
        #pragma unroll
        for (int i = 0; i < 2; i++)
            #pragma unroll
            for (int j = 0; j < 4; j++) {
                int kg = koff + m0 + ty * 2 + i;
                int nr = n0 + tx * 4 + j;
                __nv_bfloat16 h, l;
                split2(acc[i][j], h, l);
                g_Bthi[(size_t)nr * KD + kg] = h;
                g_Btlo[(size_t)nr * KD + kg] = l;
            }
        return;
    }

    if (bid < 136) {
        // ---- cbias[c] = b1[c] + sum_j (bm|bu)[j] * W1[j*256+c], 8-way split
        int cg = tid >> 3, jp = tid & 7;
        int c = (bid - 128) * 32 + cg;
        float p = 0.f;
        int j0 = jp * 64;
        #pragma unroll 4
        for (int i = 0; i < 64; i++) {
            int j = j0 + i;
            float bv = (j < 256) ? bm[j] : bu[j - 256];
            p += bv * W1[j * 256 + c];
        }
        p += __shfl_down_sync(0xFFFFFFFFu, p, 4, 8);
        p += __shfl_down_sync(0xFFFFFFFFu, p, 2, 8);
        p += __shfl_down_sync(0xFFFFFFFFu, p, 1, 8);
        if (jp == 0) g_cbias[c] = b1[c] + p;
        return;
    }

    // ---- rest ----
    int t = (bid - 136) * 256 + tid;
    if (t < KD * 16) {
        int k = t >> 4, d = t & 15;
        float s = 0.f;
        __nv_bfloat16 h, l;
        if (k < 512) {
            #pragma unroll
            for (int i = 0; i < 16; i++) s += Wm[k * 257 + i * 16 + d];
            split2(s, h, l);
            g_Bthi[(size_t)(256 + d) * KD + k] = h;
            g_Btlo[(size_t)(256 + d) * KD + k] = l;
            if (d == 0) {
                split2(Wm[k * 257 + 256], h, l);
                g_Bthi[(size_t)288 * KD + k] = h;
                g_Btlo[(size_t)288 * KD + k] = l;
            }
        } else {
            int ku = k - 512;
            #pragma unroll
            for (int i = 0; i < 16; i++) s += Wu[ku * 257 + i * 16 + d];
            split2(s, h, l);
            g_Bthi[(size_t)(272 + d) * KD + k] = h;
            g_Btlo[(size_t)(272 + d) * KD + k] = l;
            if (d == 0) {
                split2(Wu[ku * 257 + 256], h, l);
                g_Bthi[(size_t)288 * KD + k] = h;
                g_Btlo[(size_t)288 * KD + k] = l;
            }
        }
        return;
    }
    int c = t - KD * 16;
    if (c < 33) {
        int cc = 256 + c;
        float v;
        if (cc < 272) {
            int d = cc - 256; v = 0.f;
            #pragma unroll
            for (int i = 0; i < 16; i++) v += bm[i * 16 + d];
        } else if (cc < 288) {
            int d = cc - 272; v = 0.f;
            #pragma unroll
            for (int i = 0; i < 16; i++) v += bu[i * 16 + d];
        } else {
            v = bm[256] + bu[256];
        }
        g_cbias[cc] = v;
        return;
    }
    int j = c - 33;
    if (j < H2D * H1D) {
        int r = j >> 8, cc = j & 255;        // W2t[r][cc] = W2[cc][r]
        __nv_bfloat16 h, l;
        split2(W2[cc * H2D + r], h, l);
        g_W2thi[j] = h; g_W2tlo[j] = l;
    }
}

// ---------------------------------------------------------------------------
// K1: main mma.sync GEMM with fused fp32->bf16 hi/lo split of A.
// C[16384, 320] = A[16384,1024 fp32] (x) Bt(hi/lo)[320,1024]^T, 3 split terms.
// 128 CTAs (one wave), 512 thr (16 warps, 4M x 4N, warp 32x80), K-chunk=64,
// 2-stage double buffer (112KB/stage). 16 syncs total; A/Bhi fragments reused.
// ---------------------------------------------------------------------------
#define CK         64
#define NCHUNK     16
#define AHI_OFF    0
#define ALO_OFF    16384
#define BHI_OFF    32768
#define BLO_OFF    73728
#define MAIN_STAGE 114688                     // 16+16+40+40 KB
#define SMEM_MAIN  (2 * MAIN_STAGE)           // 224 KB

static __device__ __forceinline__ void ldg_a(float4* p, int ch, int m0, int t,
                                             const float* __restrict__ mv,
                                             const float* __restrict__ uv)
{
    int kc = ch * CK;
    const float* base = (kc < 512) ? (mv + kc) : (uv + kc - 512);
    #pragma unroll
    for (int l = 0; l < 4; l++) {
        int f = t + l * 512;
        int row = f >> 4, q = f & 15;
        p[l] = *reinterpret_cast<const float4*>(base + (size_t)(m0 + row) * 512 + q * 4);
    }
}

static __device__ __forceinline__ void sts_a(const float4* p, uint32_t stg, int t)
{
    #pragma unroll
    for (int l = 0; l < 4; l++) {
        int f = t + l * 512;
        int row = f >> 4, q = f & 15;
        __nv_bfloat16 h0, l0, h1, l1, h2, l2, h3, l3;
        split2(p[l].x, h0, l0); split2(p[l].y, h1, l1);
        split2(p[l].z, h2, l2); split2(p[l].w, h3, l3);
        uint32_t hi0 = pack_bf2(h0, h1), hi1 = pack_bf2(h2, h3);
        uint32_t lo0 = pack_bf2(l0, l1), lo1 = pack_bf2(l2, l3);
        uint32_t off = SWZ(row * 128 + q * 8);
        asm volatile("st.shared.v2.b32 [%0], {%1,%2};"
                     :: "r"(stg + AHI_OFF + off), "r"(hi0), "r"(hi1) : "memory");
        asm volatile("st.shared.v2.b32 [%0], {%1,%2};"
                     :: "r"(stg + ALO_OFF + off), "r"(lo0), "r"(lo1) : "memory");
    }
}

static __device__ __forceinline__ void cp_b(uint32_t stg, int ch, int t)
{
    int kc = ch * CK;
    #pragma unroll
    for (int l = 0; l < 10; l++) {
        int f = t + l * 512;                  // 0..5119: 2560 hi + 2560 lo units
        int lobuf = f >= 2560;
        int fr = lobuf ? f - 2560 : f;
        int row = fr >> 3, u = fr & 7;
        const __nv_bfloat16* src = (lobuf ? g_Btlo : g_Bthi) + (size_t)row * KD + kc + u * 8;
        cp16(stg + (lobuf ? BLO_OFF : BHI_OFF) + SWZ(row * 128 + u * 16), src);
    }
}

static __device__ __forceinline__ void chunk_ks(uint32_t stg, int ks,
                                                int wm, int wn,
                                                int a_row, int a_koff,
                                                int b_row, int b_koff,
                                                float c[2][10][4])
{
    uint32_t ahi[2][4], alo[2][4];
    #pragma unroll
    for (int mt = 0; mt < 2; mt++) {
        uint32_t ra = SWZ((wm * 32 + mt * 16 + a_row) * 128 + ks * 32 + a_koff);
        LDSM4(ahi[mt][0], ahi[mt][1], ahi[mt][2], ahi[mt][3], stg + AHI_OFF + ra);
        LDSM4(alo[mt][0], alo[mt][1], alo[mt][2], alo[mt][3], stg + ALO_OFF + ra);
    }
    #pragma unroll
    for (int jp = 0; jp < 5; jp++) {
        uint32_t rb = SWZ((wn * 80 + jp * 16 + b_row) * 128 + ks * 32 + b_koff);
        uint32_t b0[2], b1[2];
        LDSM4(b0[0], b0[1], b1[0], b1[1], stg + BHI_OFF + rb);   // Bhi
        #pragma unroll
        for (int mt = 0; mt < 2; mt++) {
            MMA16816(c[mt][2 * jp],     ahi[mt], b0);
            MMA16816(c[mt][2 * jp + 1], ahi[mt], b1);
            MMA16816(c[mt][2 * jp],     alo[mt], b0);
            MMA16816(c[mt][2 * jp + 1], alo[mt], b1);
        }
        LDSM4(b0[0], b0[1], b1[0], b1[1], stg + BLO_OFF + rb);   // Blo
        #pragma unroll
        for (int mt = 0; mt < 2; mt++) {
            MMA16816(c[mt][2 * jp],     ahi[mt], b0);
            MMA16816(c[mt][2 * jp + 1], ahi[mt], b1);
        }
    }
}

__global__ __launch_bounds__(512, 1) void k_mma_main(
    const float* __restrict__ mv, const float* __restrict__ uv)
{
    extern __shared__ char smem[];
    uint32_t sb = smem_u32(smem);
    int t = threadIdx.x;
    int lane = t & 31, wid = t >> 5;
    int wm = wid & 3, wn = wid >> 2;          // 4M x 4N warps
    int m0 = blockIdx.x * 128;

    float c[2][10][4];
    #pragma unroll
    for (int i = 0; i < 2; i++)
        #pragma unroll
        for (int j = 0; j < 10; j++)
            #pragma unroll
            for (int q = 0; q < 4; q++) c[i][j][q] = 0.f;

    int a_row  = (lane & 15);
    int a_koff = (lane >> 4) * 16;
    int b_row  = ((lane >> 4) & 1) * 8 + (lane & 7);
    int b_koff = ((lane >> 3) & 1) * 16;

    // Prologue: chunk 0.
    {
        float4 q0[4];
        ldg_a(q0, 0, m0, t, mv, uv);
        cp_b(sb, 0, t); CP_COMMIT();
        sts_a(q0, sb, t);
    }

    float4 pf[4];
    #pragma unroll 1
    for (int ic = 0; ic < NCHUNK; ic++) {
        bool pfv = (ic + 1 < NCHUNK);
        if (pfv) ldg_a(pf, ic + 1, m0, t, mv, uv);   // LDG issued a chunk ahead
        CP_WAIT0();                                   // B(ic) arrived
        __syncthreads();                              // compute(ic-1) done -> other stage free
        uint32_t nstg = sb + ((ic + 1) & 1) * MAIN_STAGE;
        if (pfv) cp_b(nstg, ic + 1, t);
        CP_COMMIT();

        uint32_t stg = sb + (ic & 1) * MAIN_STAGE;
        chunk_ks(stg, 0, wm, wn, a_row, a_koff, b_row, b_koff, c);
        chunk_ks(stg, 1, wm, wn, a_row, a_koff, b_row, b_koff, c);
        if (pfv) sts_a(pf, nstg, t);                  // A(ic+1): LDG latency hidden by ks 0-1
        chunk_ks(stg, 2, wm, wn, a_row, a_koff, b_row, b_koff, c);
        chunk_ks(stg, 3, wm, wn, a_row, a_koff, b_row, b_koff, c);
    }

    // Epilogue: bias, relu, split / route.
    #pragma unroll
    for (int mt = 0; mt < 2; mt++) {
        int rbase = m0 + wm * 32 + mt * 16 + (lane >> 2);
        #pragma unroll
        for (int half = 0; half < 2; half++) {
            int m = rbase + half * 8;
            #pragma unroll
            for (int j = 0; j < 10; j++) {
                int n = wn * 80 + j * 8 + (lane & 3) * 2;
                float v0 = c[mt][j][half * 2 + 0] + g_cbias[n < NOUT ? n : 0];
                float v1 = c[mt][j][half * 2 + 1] + g_cbias[(n + 1) < NOUT ? (n + 1) : 0];
                if (n < 256) {
                    v0 = fmaxf(v0, 0.f); v1 = fmaxf(v1, 0.f);
                    __nv_bfloat16 h0, l0, h1, l1;
                    split2(v0, h0, l0); split2(v1, h1, l1);
                    *reinterpret_cast<uint32_t*>(&g_Hhi[(size_t)m * H1D + n]) = pack_bf2(h0, h1);
                    *reinterpret_cast<uint32_t*>(&g_Hlo[(size_t)m * H1D + n]) = pack_bf2(l0, l1);
                } else {
                    #pragma unroll
                    for (int e = 0; e < 2; e++) {
                        int ne = n + e;
                        float ve = e ? v1 : v0;
                        if (ne < 272)       g_MS[m * 16 + ne - 256] = ve;
                        else if (ne < 288)  g_US[m * 16 + ne - 272] = ve;
                        else if (ne == 288) g_ADD[m] = ve;
                    }
                }
            }
        }
    }
}

// ---------------------------------------------------------------------------
// K2: tail mma.sync GEMM + final reduce, re-tiled for occupancy.
// C[16384,128] = Hcat[16384,768] @ W2tcat[128,768]^T; out = relu(.)·W3 + ...
// 256 CTAs (M=64 each), 256 thr (8 warps, 4M x 2N, warp 16x64), 2 CTAs/SM.
// ---------------------------------------------------------------------------
#define TAIL_STAGE 24576                      // 8KB A + 16KB B
#define SMEM_TAIL  (3 * TAIL_STAGE)           // 72 KB

static __device__ __forceinline__ void issue_tail(uint32_t sb, int ic, int st,
                                                  int m0, int t)
{
    int seg = ic >> 2;
    int kc  = (ic & 3) * 64;
    const __nv_bfloat16 *Ap, *Bp;
    if (seg == 0)      { Ap = g_Hhi;   Bp = g_W2thi; }
    else if (seg == 1) { Ap = g_Hlo;   Bp = g_W2thi; }
    else               { Ap = g_Hhi;   Bp = g_W2tlo; }
    uint32_t ab = sb + st * TAIL_STAGE;
    uint32_t bb = ab + 8192;
    #pragma unroll
    for (int l = 0; l < 2; l++) {             // A: 64 rows x 128B
        int f = t + l * 256;
        int row = f >> 3, kq = (f & 7) * 8;
        cp16(ab + SWZ(row * 128 + kq * 2), Ap + (size_t)(m0 + row) * H1D + kc + kq);
    }
    #pragma unroll
    for (int l = 0; l < 4; l++) {             // B: 128 rows x 128B
        int f = t + l * 256;
        int row = f >> 3, kq = (f & 7) * 8;
        cp16(bb + SWZ(row * 128 + kq * 2), Bp + (size_t)row * H1D + kc + kq);
    }
}

__global__ __launch_bounds__(256, 2) void k_mma_tail(
    const float* __restrict__ b2, const float* __restrict__ W3,
    const float* __restrict__ b3, float* __restrict__ out)
{
    extern __shared__ char smem[];
    __shared__ float b2s[128];
    __shared__ float w3s[128];
    __shared__ float ps[64][2];
    uint32_t sb = smem_u32(smem);
    int t = threadIdx.x;
    int lane = t & 31, wid = t >> 5;
    int wm = wid & 3, wn = wid >> 2;          // 4M x 2N warps, warp tile 16x64
    int m0 = blockIdx.x * 64;

    if (t < 128) { b2s[t] = b2[t]; w3s[t] = W3[t]; }

    float c[8][4];
    #pragma unroll
    for (int j = 0; j < 8; j++)
        #pragma unroll
        for (int q = 0; q < 4; q++) c[j][q] = 0.f;

    const int NC = 12;
    issue_tail(sb, 0, 0, m0, t); CP_COMMIT();
    issue_tail(sb, 1, 1, m0, t); CP_COMMIT();

    int a_row  = (lane & 15);
    int a_koff = (lane >> 4) * 16;
    int b_row  = ((lane >> 4) & 1) * 8 + (lane & 7);
    int b_koff = ((lane >> 3) & 1) * 16;

    #pragma unroll 1
    for (int ic = 0; ic < NC; ic++) {
        __syncthreads();
        if (ic + 2 < NC) issue_tail(sb, ic + 2, (ic + 2) % 3, m0, t);
        CP_COMMIT();
        CP_WAIT2();
        __syncthreads();

        uint32_t ab = sb + (ic % 3) * TAIL_STAGE;
        uint32_t bb = ab + 8192;
        #pragma unroll
        for (int ks = 0; ks < 4; ks++) {
            uint32_t a[4], b[8][2];
            LDSM4(a[0], a[1], a[2], a[3],
                  ab + SWZ((wm * 16 + a_row) * 128 + ks * 32 + a_koff));
            #pragma unroll
            for (int jp = 0; jp < 4; jp++)
                LDSM4(b[2 * jp][0], b[2 * jp][1], b[2 * jp + 1][0], b[2 * jp + 1][1],
                      bb + SWZ((wn * 64 + jp * 16 + b_row) * 128 + ks * 32 + b_koff));
            #pragma unroll
            for (int j = 0; j < 8; j++)
                MMA16816(c[j], a, b[j]);
        }
    }

    // Epilogue: relu(c + b2) dot W3 over this warp's 64 cols, lane-reduce,
    // then cross-warp (wn) reduce via smem.
    float p0 = 0.f, p1 = 0.f;
    #pragma unroll
    for (int j = 0; j < 8; j++) {
        int n = wn * 64 + j * 8 + (lane & 3) * 2;
        p0 += fmaxf(c[j][0] + b2s[n],     0.f) * w3s[n];
        p0 += fmaxf(c[j][1] + b2s[n + 1], 0.f) * w3s[n + 1];
        p1 += fmaxf(c[j][2] + b2s[n],     0.f) * w3s[n];
        p1 += fmaxf(c[j][3] + b2s[n + 1], 0.f) * w3s[n + 1];
    }
    p0 += __shfl_xor_sync(0xFFFFFFFF, p0, 1);
    p0 += __shfl_xor_sync(0xFFFFFFFF, p0, 2);
    p1 += __shfl_xor_sync(0xFFFFFFFF, p1, 1);
    p1 += __shfl_xor_sync(0xFFFFFFFF, p1, 2);
    if ((lane & 3) == 0) {
        ps[wm * 16 + (lane >> 2)][wn]     = p0;
        ps[wm * 16 + (lane >> 2) + 8][wn] = p1;
    }
    __syncthreads();

    if (t < 64) {
        int m = m0 + t;
        float s = b3[0] + g_ADD[m] + ps[t][0] + ps[t][1];
        #pragma unroll
        for (int i = 0; i < 16; i++) s += g_MS[m * 16 + i] * g_US[m * 16 + i];
        out[m] = s;
    }
}

// ---------------------------------------------------------------------------
extern "C" void kernel_launch(void* const* d_in, const int* in_sizes, int n_in,
                              void* d_out, int out_size)
{
    const float* mv = (const float*)d_in[0];
    const float* uv = (const float*)d_in[1];
    const float* Wm = (const float*)d_in[2];
    const float* bm = (const float*)d_in[3];
    const float* Wu = (const float*)d_in[4];
    const float* bu = (const float*)d_in[5];
    const float* W1 = (const float*)d_in[6];
    const float* b1 = (const float*)d_in[7];
    const float* W2 = (const float*)d_in[8];
    const float* b2 = (const float*)d_in[9];
    const float* W3 = (const float*)d_in[10];
    const float* b3 = (const float*)d_in[11];
    float* out = (float*)d_out;

    cudaFuncSetAttribute(k_pre,      cudaFuncAttributeMaxDynamicSharedMemorySize, PRE_SMEM);
    cudaFuncSetAttribute(k_mma_main, cudaFuncAttributeMaxDynamicSharedMemorySize, SMEM_MAIN);
    cudaFuncSetAttribute(k_mma_tail, cudaFuncAttributeMaxDynamicSharedMemorySize, SMEM_TAIL);

    // Merged precompute: 128 single-sync combine + 8 bias + rest blocks.
    const int PRE_BLKS = 136 + (KD * 16 + 33 + H2D * H1D + 255) / 256;
    k_pre<<<PRE_BLKS, 256, PRE_SMEM>>>(Wm, bm, Wu, bu, W1, b1, W2);

    // Main tensor-core GEMM, one wave of 128 CTAs, 2-stage CK=64 pipeline.
    k_mma_main<<<BATCH / 128, 512, SMEM_MAIN>>>(mv, uv);

    // Tail tensor-core GEMM + final reduction, 256 CTAs, 2/SM.
    k_mma_tail<<<BATCH / 64, 256, SMEM_TAIL>>>(b2, W3, b3, out);
}

// round 14
// speedup vs baseline: 1.5247x; 1.1513x over previous
#include <cuda_runtime.h>
#include <cuda_bf16.h>
#include <cstdint>

#define BATCH 16384
#define KD    1024
#define NOUT  289
#define H1D   256
#define H2D   128

// ---------------------------------------------------------------------------
// Device scratch (zero-initialized at load; Bt pad rows 289..319 stay 0).
// ---------------------------------------------------------------------------
__device__ float         g_cbias[NOUT];
__device__ __nv_bfloat16 g_Bthi[320 * KD];
__device__ __nv_bfloat16 g_Btlo[320 * KD];
__device__ __nv_bfloat16 g_W2thi[H2D * H1D];
__device__ __nv_bfloat16 g_W2tlo[H2D * H1D];

// ---------------------------------------------------------------------------
// Helpers (base sm_103 PTX only: mma.sync / ldmatrix / cp.async)
// ---------------------------------------------------------------------------
static __device__ __forceinline__ uint32_t smem_u32(const void* p) {
    uint32_t a;
    asm("{ .reg .u64 t; cvta.to.shared.u64 t, %1; cvt.u32.u64 %0, t; }" : "=r"(a) : "l"(p));
    return a;
}
static __device__ __forceinline__ void cp16(uint32_t dst, const void* src) {
    asm volatile("cp.async.cg.shared.global [%0], [%1], 16;\n" :: "r"(dst), "l"(src));
}
#define CP_COMMIT() asm volatile("cp.async.commit_group;\n" ::: "memory")
#define CP_WAIT0()  asm volatile("cp.async.wait_group 0;\n" ::: "memory")

#define LDSM4(r0, r1, r2, r3, addr) \
    asm volatile("ldmatrix.sync.aligned.m8n8.x4.shared.b16 {%0,%1,%2,%3}, [%4];" \
                 : "=r"(r0), "=r"(r1), "=r"(r2), "=r"(r3) : "r"(addr))

#define MMA16816(c, a, b) \
    asm volatile("mma.sync.aligned.m16n8k16.row.col.f32.bf16.bf16.f32 " \
                 "{%0,%1,%2,%3},{%4,%5,%6,%7},{%8,%9},{%0,%1,%2,%3};" \
                 : "+f"((c)[0]), "+f"((c)[1]), "+f"((c)[2]), "+f"((c)[3]) \
                 : "r"((a)[0]), "r"((a)[1]), "r"((a)[2]), "r"((a)[3]), \
                   "r"((b)[0]), "r"((b)[1]))

#define SWZ(x)   ((x) ^ (((x) >> 3) & 0x70))   // 128B-row swizzle

static __device__ __forceinline__ void split2(float v, __nv_bfloat16& h, __nv_bfloat16& l) {
    h = __float2bfloat16(v);
    l = __float2bfloat16(v - __bfloat162float(h));
}
static __device__ __forceinline__ uint32_t pack_bf2(__nv_bfloat16 a, __nv_bfloat16 b) {
    __nv_bfloat162 p; p.x = a; p.y = b;
    return *reinterpret_cast<uint32_t*>(&p);
}

// ---------------------------------------------------------------------------
// K0a: combine GEMM (128 blocks, 99KB smem): Bt[n,kglob] = (Wm|Wu)@W1half,
// full-K strips, ONE sync, fully-unrolled A loads (MLP ~32).
// ---------------------------------------------------------------------------
#define PRE_SMEM ((256 * 33 + 256 * 64) * 4)   // 99328 bytes

__global__ __launch_bounds__(256) void k_pre_combine(
    const float* __restrict__ Wm, const float* __restrict__ Wu,
    const float* __restrict__ W1)
{
    extern __shared__ float dsm[];
    int bid = blockIdx.x;
    int tid = threadIdx.x;

    int z   = bid >> 6;                   // tower
    int rem = bid & 63;                   // 16 mblk x 4 nblk
    const float* A  = (z == 0) ? Wm : Wu;
    const float* Bw = (z == 0) ? W1 : (W1 + 256 * 256);
    int koff        = (z == 0) ? 0  : 512;
    const int lda = 257, ldb = 256;

    int m0 = (rem >> 2) * 32, n0 = (rem & 3) * 64;
    float* As = dsm;                      // [256 k][33 m-pad]
    float* Bs = dsm + 256 * 33;           // [256 k][64 n]

    // A strip: 32 rows x 256 k; full unroll -> all 32 LDGs in flight.
    #pragma unroll
    for (int r = 0; r < 32; r++)
        As[tid * 33 + r] = A[(m0 + r) * lda + tid];
    // B strip: 256 k x 64 n, float4 coalesced.
    #pragma unroll
    for (int i = 0; i < 16; i++) {
        int f = i * 256 + tid;
        int k = f >> 4, nq = (f & 15) * 4;
        float4 v = *reinterpret_cast<const float4*>(Bw + k * ldb + n0 + nq);
        *reinterpret_cast<float4*>(&Bs[k * 64 + nq]) = v;
    }
    __syncthreads();                      // the ONLY barrier

    int tx = tid & 15, ty = tid >> 4;     // m = ty*2+i, n = tx*4+j
    float acc[2][4] = {};
    #pragma unroll 8
    for (int k = 0; k < 256; k++) {
        float a0 = As[k * 33 + ty * 2];
        float a1 = As[k * 33 + ty * 2 + 1];
        float4 b = *reinterpret_cast<const float4*>(&Bs[k * 64 + tx * 4]);
        acc[0][0] += a0 * b.x; acc[0][1] += a0 * b.y;
        acc[0][2] += a0 * b.z; acc[0][3] += a0 * b.w;
        acc[1][0] += a1 * b.x; acc[1][1] += a1 * b.y;
        acc[1][2] += a1 * b.z; acc[1][3] += a1 * b.w;
    }
    #pragma unroll
    for (int i = 0; i < 2; i++)
        #pragma unroll
        for (int j = 0; j < 4; j++) {
            int kg = koff + m0 + ty * 2 + i;
            int nr = n0 + tx * 4 + j;
            __nv_bfloat16 h, l;
            split2(acc[i][j], h, l);
            g_Bthi[(size_t)nr * KD + kg] = h;
            g_Btlo[(size_t)nr * KD + kg] = l;
        }
}

// ---------------------------------------------------------------------------
// K0b: rest (NO dynamic smem -> high occupancy).
//   blocks [0,8):  cbias[0:256] via 8-way j-split + shfl reduce
//   blocks [8,..): ms/us/add rows of Bt, cbias[256:289], W2t split
// ---------------------------------------------------------------------------
__global__ __launch_bounds__(256) void k_pre_rest(
    const float* __restrict__ Wm, const float* __restrict__ bm,
    const float* __restrict__ Wu, const float* __restrict__ bu,
    const float* __restrict__ W1, const float* __restrict__ b1,
    const float* __restrict__ W2)
{
    int bid = blockIdx.x;
    int tid = threadIdx.x;

    if (bid < 8) {
        int cg = tid >> 3, jp = tid & 7;
        int c = bid * 32 + cg;
        float p = 0.f;
        int j0 = jp * 64;
        #pragma unroll 4
        for (int i = 0; i < 64; i++) {
            int j = j0 + i;
            float bv = (j < 256) ? bm[j] : bu[j - 256];
            p += bv * W1[j * 256 + c];
        }
        p += __shfl_down_sync(0xFFFFFFFFu, p, 4, 8);
        p += __shfl_down_sync(0xFFFFFFFFu, p, 2, 8);
        p += __shfl_down_sync(0xFFFFFFFFu, p, 1, 8);
        if (jp == 0) g_cbias[c] = b1[c] + p;
        return;
    }

    int t = (bid - 8) * 256 + tid;
    if (t < KD * 16) {
        int k = t >> 4, d = t & 15;
        float s = 0.f;
        __nv_bfloat16 h, l;
        if (k < 512) {
            #pragma unroll
            for (int i = 0; i < 16; i++) s += Wm[k * 257 + i * 16 + d];
            split2(s, h, l);
            g_Bthi[(size_t)(256 + d) * KD + k] = h;
            g_Btlo[(size_t)(256 + d) * KD + k] = l;
            if (d == 0) {
                split2(Wm[k * 257 + 256], h, l);
                g_Bthi[(size_t)288 * KD + k] = h;
                g_Btlo[(size_t)288 * KD + k] = l;
            }
        } else {
            int ku = k - 512;
            #pragma unroll
            for (int i = 0; i < 16; i++) s += Wu[ku * 257 + i * 16 + d];
            split2(s, h, l);
            g_Bthi[(size_t)(272 + d) * KD + k] = h;
            g_Btlo[(size_t)(272 + d) * KD + k] = l;
            if (d == 0) {
                split2(Wu[ku * 257 + 256], h, l);
                g_Bthi[(size_t)288 * KD + k] = h;
                g_Btlo[(size_t)288 * KD + k] = l;
            }
        }
        return;
    }
    int c = t - KD * 16;
    if (c < 33) {
        int cc = 256 + c;
        float v;
        if (cc < 272) {
            int d = cc - 256; v = 0.f;
            #pragma unroll
            for (int i = 0; i < 16; i++) v += bm[i * 16 + d];
        } else if (cc < 288) {
            int d = cc - 272; v = 0.f;
            #pragma unroll
            for (int i = 0; i < 16; i++) v += bu[i * 16 + d];
        } else {
            v = bm[256] + bu[256];
        }
        g_cbias[cc] = v;
        return;
    }
    int j = c - 33;
    if (j < H2D * H1D) {
        int r = j >> 8, cc = j & 255;        // W2t[r][cc] = W2[cc][r]
        __nv_bfloat16 h, l;
        split2(W2[cc * H2D + r], h, l);
        g_W2thi[j] = h; g_W2tlo[j] = l;
    }
}

// ---------------------------------------------------------------------------
// K1: FUSED main + tail.
// Phase 1 (main): C[16384,320] = A[16384,1024 fp32] (x) Bt(hi/lo)^T, 3 terms,
//   128 CTAs, 512 thr (16 warps 4Mx4N, warp 32x80), CK=64, 2-stage.
// Phase 2 (tail, same CTA): h1(128x256) held in SMEM as bf16 hi/lo; W2t hi/lo
//   streamed via cp.async; 128x128x768 GEMM (warp 32x32); relu·W3 + FM + out.
// ---------------------------------------------------------------------------
#define CK         64
#define NCHUNK     16
#define AHI_OFF    0
#define ALO_OFF    16384
#define BHI_OFF    32768
#define BLO_OFF    73728
#define MAIN_STAGE 114688                     // 16+16+40+40 KB
#define SMEM_MAIN  (2 * MAIN_STAGE)           // 224 KB

// Tail overlay offsets (valid after main loop's final sync):
#define TH_HI   0                             // 4 chunks x 16KB = 64KB
#define TH_LO   65536                         // 64KB
#define TW2     131072                        // 2 bufs x 32KB (hi 16K + lo 16K)
#define TMSUS   196608                        // 128 rows x 36 floats = 18KB
#define TB2     215040                        // 128 floats
#define TW3     215552                        // 128 floats
#define TPS     216064                        // 128 x 4 floats

static __device__ __forceinline__ void ldg_a(float4* p, int ch, int m0, int t,
                                             const float* __restrict__ mv,
                                             const float* __restrict__ uv)
{
    int kc = ch * CK;
    const float* base = (kc < 512) ? (mv + kc) : (uv + kc - 512);
    #pragma unroll
    for (int l = 0; l < 4; l++) {
        int f = t + l * 512;
        int row = f >> 4, q = f & 15;
        p[l] = *reinterpret_cast<const float4*>(base + (size_t)(m0 + row) * 512 + q * 4);
    }
}

static __device__ __forceinline__ void sts_a(const float4* p, uint32_t stg, int t)
{
    #pragma unroll
    for (int l = 0; l < 4; l++) {
        int f = t + l * 512;
        int row = f >> 4, q = f & 15;
        __nv_bfloat16 h0, l0, h1, l1, h2, l2, h3, l3;
        split2(p[l].x, h0, l0); split2(p[l].y, h1, l1);
        split2(p[l].z, h2, l2); split2(p[l].w, h3, l3);
        uint32_t hi0 = pack_bf2(h0, h1), hi1 = pack_bf2(h2, h3);
        uint32_t lo0 = pack_bf2(l0, l1), lo1 = pack_bf2(l2, l3);
        uint32_t off = SWZ(row * 128 + q * 8);
        asm volatile("st.shared.v2.b32 [%0], {%1,%2};"
                     :: "r"(stg + AHI_OFF + off), "r"(hi0), "r"(hi1) : "memory");
        asm volatile("st.shared.v2.b32 [%0], {%1,%2};"
                     :: "r"(stg + ALO_OFF + off), "r"(lo0), "r"(lo1) : "memory");
    }
}

static __device__ __forceinline__ void cp_b(uint32_t stg, int ch, int t)
{
    int kc = ch * CK;
    #pragma unroll
    for (int l = 0; l < 10; l++) {
        int f = t + l * 512;                  // 0..5119: 2560 hi + 2560 lo units
        int lobuf = f >= 2560;
        int fr = lobuf ? f - 2560 : f;
        int row = fr >> 3, u = fr & 7;
        const __nv_bfloat16* src = (lobuf ? g_Btlo : g_Bthi) + (size_t)row * KD + kc + u * 8;
        cp16(stg + (lobuf ? BLO_OFF : BHI_OFF) + SWZ(row * 128 + u * 16), src);
    }
}

static __device__ __forceinline__ void cp_w2(uint32_t sb, int buf, int ch, int t)
{
    int kc = ch * 64;
    #pragma unroll
    for (int l = 0; l < 4; l++) {
        int f = t + l * 512;                  // 0..2047: 1024 hi + 1024 lo
        int lo = f >= 1024;
        int fr = lo ? f - 1024 : f;
        int row = fr >> 3, u = fr & 7;
        const __nv_bfloat16* src = (lo ? g_W2tlo : g_W2thi) + row * H1D + kc + u * 8;
        cp16(sb + TW2 + buf * 32768 + (lo ? 16384 : 0) + SWZ(row * 128 + u * 16), src);
    }
}

static __device__ __forceinline__ void chunk_ks(uint32_t stg, int ks,
                                                int wm, int wn,
                                                int a_row, int a_koff,
                                                int b_row, int b_koff,
                                                float c[2][10][4])
{
    uint32_t ahi[2][4], alo[2][4];
    #pragma unroll
    for (int mt = 0; mt < 2; mt++) {
        uint32_t ra = SWZ((wm * 32 + mt * 16 + a_row) * 128 + ks * 32 + a_koff);
        LDSM4(ahi[mt][0], ahi[mt][1], ahi[mt][2], ahi[mt][3], stg + AHI_OFF + ra);
        LDSM4(alo[mt][0], alo[mt][1], alo[mt][2], alo[mt][3], stg + ALO_OFF + ra);
    }
    #pragma unroll
    for (int jp = 0; jp < 5; jp++) {
        uint32_t rb = SWZ((wn * 80 + jp * 16 + b_row) * 128 + ks * 32 + b_koff);
        uint32_t b0[2], b1[2];
        LDSM4(b0[0], b0[1], b1[0], b1[1], stg + BHI_OFF + rb);   // Bhi
        #pragma unroll
        for (int mt = 0; mt < 2; mt++) {
            MMA16816(c[mt][2 * jp],     ahi[mt], b0);
            MMA16816(c[mt][2 * jp + 1], ahi[mt], b1);
            MMA16816(c[mt][2 * jp],     alo[mt], b0);
            MMA16816(c[mt][2 * jp + 1], alo[mt], b1);
        }
        LDSM4(b0[0], b0[1], b1[0], b1[1], stg + BLO_OFF + rb);   // Blo
        #pragma unroll
        for (int mt = 0; mt < 2; mt++) {
            MMA16816(c[mt][2 * jp],     ahi[mt], b0);
            MMA16816(c[mt][2 * jp + 1], ahi[mt], b1);
        }
    }
}

__global__ __launch_bounds__(512, 1) void k_mma_main(
    const float* __restrict__ mv, const float* __restrict__ uv,
    const float* __restrict__ b2, const float* __restrict__ W3,
    const float* __restrict__ b3, float* __restrict__ out)
{
    extern __shared__ char smem[];
    uint32_t sb = smem_u32(smem);
    int t = threadIdx.x;
    int lane = t & 31, wid = t >> 5;
    int wm = wid & 3, wn = wid >> 2;          // 4M x 4N warps
    int m0 = blockIdx.x * 128;

    float c[2][10][4];
    #pragma unroll
    for (int i = 0; i < 2; i++)
        #pragma unroll
        for (int j = 0; j < 10; j++)
            #pragma unroll
            for (int q = 0; q < 4; q++) c[i][j][q] = 0.f;

    int a_row  = (lane & 15);
    int a_koff = (lane >> 4) * 16;
    int b_row  = ((lane >> 4) & 1) * 8 + (lane & 7);
    int b_koff = ((lane >> 3) & 1) * 16;

    // ---------------- Phase 1: main GEMM ----------------
    {
        float4 q0[4];
        ldg_a(q0, 0, m0, t, mv, uv);
        cp_b(sb, 0, t); CP_COMMIT();
        sts_a(q0, sb, t);
    }

    float4 pf[4];
    #pragma unroll 1
    for (int ic = 0; ic < NCHUNK; ic++) {
        bool pfv = (ic + 1 < NCHUNK);
        if (pfv) ldg_a(pf, ic + 1, m0, t, mv, uv);
        CP_WAIT0();
        __syncthreads();
        uint32_t nstg = sb + ((ic + 1) & 1) * MAIN_STAGE;
        if (pfv) cp_b(nstg, ic + 1, t);
        CP_COMMIT();

        uint32_t stg = sb + (ic & 1) * MAIN_STAGE;
        chunk_ks(stg, 0, wm, wn, a_row, a_koff, b_row, b_koff, c);
        chunk_ks(stg, 1, wm, wn, a_row, a_koff, b_row, b_koff, c);
        if (pfv) sts_a(pf, nstg, t);
        chunk_ks(stg, 2, wm, wn, a_row, a_koff, b_row, b_koff, c);
        chunk_ks(stg, 3, wm, wn, a_row, a_koff, b_row, b_koff, c);
    }

    __syncthreads();   // all warps done reading stage smem -> overlay is safe

    // ---------------- Epilogue: bias+relu, H -> SMEM, ms/us/add -> SMEM ----
    float b2v = 0.f, w3v = 0.f;
    if (t < 128) { b2v = b2[t]; w3v = W3[t]; }   // prefetch (LDG latency hidden)

    #pragma unroll
    for (int mt = 0; mt < 2; mt++) {
        #pragma unroll
        for (int half = 0; half < 2; half++) {
            int r = wm * 32 + mt * 16 + (lane >> 2) + half * 8;  // CTA-local row
            #pragma unroll
            for (int j = 0; j < 10; j++) {
                int n = wn * 80 + j * 8 + (lane & 3) * 2;
                float v0 = c[mt][j][half * 2 + 0] + g_cbias[n < NOUT ? n : 0];
                float v1 = c[mt][j][half * 2 + 1] + g_cbias[(n + 1) < NOUT ? (n + 1) : 0];
                if (n < 256) {
                    v0 = fmaxf(v0, 0.f); v1 = fmaxf(v1, 0.f);
                    __nv_bfloat16 h0, l0, h1, l1;
                    split2(v0, h0, l0); split2(v1, h1, l1);
                    uint32_t off = (n >> 6) * 16384 + SWZ(r * 128 + (n & 63) * 2);
                    *reinterpret_cast<uint32_t*>(smem + TH_HI + off) = pack_bf2(h0, h1);
                    *reinterpret_cast<uint32_t*>(smem + TH_LO + off) = pack_bf2(l0, l1);
                } else {
                    float* msus = reinterpret_cast<float*>(smem + TMSUS) + r * 36;
                    #pragma unroll
                    for (int e = 0; e < 2; e++) {
                        int ne = n + e;
                        float ve = e ? v1 : v0;
                        if (ne < 272)       msus[ne - 256] = ve;        // ms
                        else if (ne < 288)  msus[16 + ne - 272] = ve;   // us
                        else if (ne == 288) msus[32] = ve;              // add
                    }
                }
            }
        }
    }
    if (t < 128) {
        reinterpret_cast<float*>(smem + TB2)[t] = b2v;
        reinterpret_cast<float*>(smem + TW3)[t] = w3v;
    }
    cp_w2(sb, 0, 0, t); CP_COMMIT();

    // ---------------- Phase 2: tail GEMM (warp = 32 rows x 32 cols) --------
    float a2[2][4][4];
    #pragma unroll
    for (int i = 0; i < 2; i++)
        #pragma unroll
        for (int j = 0; j < 4; j++)
            #pragma unroll
            for (int q = 0; q < 4; q++) a2[i][j][q] = 0.f;

    #pragma unroll 1
    for (int ch = 0; ch < 4; ch++) {
        CP_WAIT0();
        __syncthreads();            // W2(ch) ready; prior readers of other buf done
        if (ch + 1 < 4) cp_w2(sb, (ch + 1) & 1, ch + 1, t);
        CP_COMMIT();

        uint32_t hh  = sb + TH_HI + ch * 16384;
        uint32_t hl  = sb + TH_LO + ch * 16384;
        uint32_t w2h = sb + TW2 + (ch & 1) * 32768;
        uint32_t w2l = w2h + 16384;
        #pragma unroll
        for (int ks = 0; ks < 4; ks++) {
            uint32_t ahi[2][4], alo[2][4];
            #pragma unroll
            for (int mt = 0; mt < 2; mt++) {
                uint32_t ra = SWZ((wm * 32 + mt * 16 + a_row) * 128 + ks * 32 + a_koff);
                LDSM4(ahi[mt][0], ahi[mt][1], ahi[mt][2], ahi[mt][3], hh + ra);
                LDSM4(alo[mt][0], alo[mt][1], alo[mt][2], alo[mt][3], hl + ra);
            }
            uint32_t bh[4][2], bl[4][2];
            #pragma unroll
            for (int jp = 0; jp < 2; jp++) {
                uint32_t rb = SWZ((wn * 32 + jp * 16 + b_row) * 128 + ks * 32 + b_koff);
                LDSM4(bh[2 * jp][0], bh[2 * jp][1], bh[2 * jp + 1][0], bh[2 * jp + 1][1], w2h + rb);
                LDSM4(bl[2 * jp][0], bl[2 * jp][1], bl[2 * jp + 1][0], bl[2 * jp + 1][1], w2l + rb);
            }
            #pragma unroll
            for (int mt = 0; mt < 2; mt++)
                #pragma unroll
                for (int j = 0; j < 4; j++) {
                    MMA16816(a2[mt][j], ahi[mt], bh[j]);
                    MMA16816(a2[mt][j], alo[mt], bh[j]);
                    MMA16816(a2[mt][j], ahi[mt], bl[j]);
                }
        }
    }

    // relu(+b2)·w3 over this warp's 32 cols, lane-reduce, cross-warp via smem.
    const float* b2s = reinterpret_cast<const float*>(smem + TB2);
    const float* w3s = reinterpret_cast<const float*>(smem + TW3);
    float* ps = reinterpret_cast<float*>(smem + TPS);
    #pragma unroll
    for (int mt = 0; mt < 2; mt++) {
        float p0 = 0.f, p1 = 0.f;
        #pragma unroll
        for (int j = 0; j < 4; j++) {
            int n = wn * 32 + j * 8 + (lane & 3) * 2;
            p0 += fmaxf(a2[mt][j][0] + b2s[n],     0.f) * w3s[n];
            p0 += fmaxf(a2[mt][j][1] + b2s[n + 1], 0.f) * w3s[n + 1];
            p1 += fmaxf(a2[mt][j][2] + b2s[n],     0.f) * w3s[n];
            p1 += fmaxf(a2[mt][j][3] + b2s[n + 1], 0.f) * w3s[n + 1];
        }
        p0 += __shfl_xor_sync(0xFFFFFFFF, p0, 1);
        p0 += __shfl_xor_sync(0xFFFFFFFF, p0, 2);
        p1 += __shfl_xor_sync(0xFFFFFFFF, p1, 1);
        p1 += __shfl_xor_sync(0xFFFFFFFF, p1, 2);
        if ((lane & 3) == 0) {
            int r0 = wm * 32 + mt * 16 + (lane >> 2);
            ps[r0 * 4 + wn]       = p0;
            ps[(r0 + 8) * 4 + wn] = p1;
        }
    }
    __syncthreads();

    if (t < 128) {
        const float* msus = reinterpret_cast<const float*>(smem + TMSUS) + t * 36;
        float s = b3[0] + msus[32] + ps[t * 4] + ps[t * 4 + 1] + ps[t * 4 + 2] + ps[t * 4 + 3];
        #pragma unroll
        for (int i = 0; i < 16; i++) s += msus[i] * msus[16 + i];
        out[m0 + t] = s;
    }
}

// ---------------------------------------------------------------------------
extern "C" void kernel_launch(void* const* d_in, const int* in_sizes, int n_in,
                              void* d_out, int out_size)
{
    const float* mv = (const float*)d_in[0];
    const float* uv = (const float*)d_in[1];
    const float* Wm = (const float*)d_in[2];
    const float* bm = (const float*)d_in[3];
    const float* Wu = (const float*)d_in[4];
    const float* bu = (const float*)d_in[5];
    const float* W1 = (const float*)d_in[6];
    const float* b1 = (const float*)d_in[7];
    const float* W2 = (const float*)d_in[8];
    const float* b2 = (const float*)d_in[9];
    const float* W3 = (const float*)d_in[10];
    const float* b3 = (const float*)d_in[11];
    float* out = (float*)d_out;

    cudaFuncSetAttribute(k_pre_combine, cudaFuncAttributeMaxDynamicSharedMemorySize, PRE_SMEM);
    cudaFuncSetAttribute(k_mma_main,    cudaFuncAttributeMaxDynamicSharedMemorySize, SMEM_MAIN);

    // Precompute: big-smem combine blocks and zero-smem rest blocks split so
    // the rest grid isn't occupancy-capped by the 99KB reservation.
    k_pre_rest<<<8 + (KD * 16 + 33 + H2D * H1D + 255) / 256, 256>>>(Wm, bm, Wu, bu, W1, b1, W2);
    k_pre_combine<<<128, 256, PRE_SMEM>>>(Wm, Wu, W1);

    // Fused main + tail GEMM, one wave of 128 CTAs.
    k_mma_main<<<BATCH / 128, 512, SMEM_MAIN>>>(mv, uv, b2, W3, b3, out);
}

// round 15
// speedup vs baseline: 1.5533x; 1.0188x over previous
#include <cuda_runtime.h>
#include <cuda_bf16.h>
#include <cstdint>

#define BATCH 16384
#define KD    1024
#define NOUT  289
#define H1D   256
#define H2D   128

// ---------------------------------------------------------------------------
// Device scratch (zero-initialized at load; Bt pad rows 289..319 stay 0).
// ---------------------------------------------------------------------------
__device__ float         g_cbias[NOUT];
__device__ __nv_bfloat16 g_Bthi[320 * KD];
__device__ __nv_bfloat16 g_Btlo[320 * KD];
__device__ __nv_bfloat16 g_W2thi[H2D * H1D];
__device__ __nv_bfloat16 g_W2tlo[H2D * H1D];

// ---------------------------------------------------------------------------
// Helpers (base sm_103 PTX only: mma.sync / ldmatrix / cp.async)
// ---------------------------------------------------------------------------
static __device__ __forceinline__ uint32_t smem_u32(const void* p) {
    uint32_t a;
    asm("{ .reg .u64 t; cvta.to.shared.u64 t, %1; cvt.u32.u64 %0, t; }" : "=r"(a) : "l"(p));
    return a;
}
static __device__ __forceinline__ void cp16(uint32_t dst, const void* src) {
    asm volatile("cp.async.cg.shared.global [%0], [%1], 16;\n" :: "r"(dst), "l"(src));
}
#define CP_COMMIT() asm volatile("cp.async.commit_group;\n" ::: "memory")
#define CP_WAIT0()  asm volatile("cp.async.wait_group 0;\n" ::: "memory")

#define LDSM4(r0, r1, r2, r3, addr) \
    asm volatile("ldmatrix.sync.aligned.m8n8.x4.shared.b16 {%0,%1,%2,%3}, [%4];" \
                 : "=r"(r0), "=r"(r1), "=r"(r2), "=r"(r3) : "r"(addr))

#define MMA16816(c, a, b) \
    asm volatile("mma.sync.aligned.m16n8k16.row.col.f32.bf16.bf16.f32 " \
                 "{%0,%1,%2,%3},{%4,%5,%6,%7},{%8,%9},{%0,%1,%2,%3};" \
                 : "+f"((c)[0]), "+f"((c)[1]), "+f"((c)[2]), "+f"((c)[3]) \
                 : "r"((a)[0]), "r"((a)[1]), "r"((a)[2]), "r"((a)[3]), \
                   "r"((b)[0]), "r"((b)[1]))

#define SWZ(x)   ((x) ^ (((x) >> 3) & 0x70))   // 128B-row swizzle

static __device__ __forceinline__ void split2(float v, __nv_bfloat16& h, __nv_bfloat16& l) {
    h = __float2bfloat16(v);
    l = __float2bfloat16(v - __bfloat162float(h));
}
static __device__ __forceinline__ uint32_t pack_bf2(__nv_bfloat16 a, __nv_bfloat16 b) {
    __nv_bfloat162 p; p.x = a; p.y = b;
    return *reinterpret_cast<uint32_t*>(&p);
}

// ---------------------------------------------------------------------------
// K0a: combine GEMM (128 blocks, 99KB smem): Bt[n,kglob] = (Wm|Wu)@W1half,
// full-K strips, ONE sync, fully-unrolled A loads (MLP ~32).
// ---------------------------------------------------------------------------
#define PRE_SMEM ((256 * 33 + 256 * 64) * 4)   // 99328 bytes

__global__ __launch_bounds__(256) void k_pre_combine(
    const float* __restrict__ Wm, const float* __restrict__ Wu,
    const float* __restrict__ W1)
{
    extern __shared__ float dsm[];
    int bid = blockIdx.x;
    int tid = threadIdx.x;

    int z   = bid >> 6;                   // tower
    int rem = bid & 63;                   // 16 mblk x 4 nblk
    const float* A  = (z == 0) ? Wm : Wu;
    const float* Bw = (z == 0) ? W1 : (W1 + 256 * 256);
    int koff        = (z == 0) ? 0  : 512;
    const int lda = 257, ldb = 256;

    int m0 = (rem >> 2) * 32, n0 = (rem & 3) * 64;
    float* As = dsm;                      // [256 k][33 m-pad]
    float* Bs = dsm + 256 * 33;           // [256 k][64 n]

    // A strip: 32 rows x 256 k; full unroll -> all 32 LDGs in flight.
    #pragma unroll
    for (int r = 0; r < 32; r++)
        As[tid * 33 + r] = A[(m0 + r) * lda + tid];
    // B strip: 256 k x 64 n, float4 coalesced.
    #pragma unroll
    for (int i = 0; i < 16; i++) {
        int f = i * 256 + tid;
        int k = f >> 4, nq = (f & 15) * 4;
        float4 v = *reinterpret_cast<const float4*>(Bw + k * ldb + n0 + nq);
        *reinterpret_cast<float4*>(&Bs[k * 64 + nq]) = v;
    }
    __syncthreads();                      // the ONLY barrier

    int tx = tid & 15, ty = tid >> 4;     // m = ty*2+i, n = tx*4+j
    float acc[2][4] = {};
    #pragma unroll 8
    for (int k = 0; k < 256; k++) {
        float a0 = As[k * 33 + ty * 2];
        float a1 = As[k * 33 + ty * 2 + 1];
        float4 b = *reinterpret_cast<const float4*>(&Bs[k * 64 + tx * 4]);
        acc[0][0] += a0 * b.x; acc[0][1] += a0 * b.y;
        acc[0][2] += a0 * b.z; acc[0][3] += a0 * b.w;
        acc[1][0] += a1 * b.x; acc[1][1] += a1 * b.y;
        acc[1][2] += a1 * b.z; acc[1][3] += a1 * b.w;
    }
    #pragma unroll
    for (int i = 0; i < 2; i++)
        #pragma unroll
        for (int j = 0; j < 4; j++) {
            int kg = koff + m0 + ty * 2 + i;
            int nr = n0 + tx * 4 + j;
            __nv_bfloat16 h, l;
            split2(acc[i][j], h, l);
            g_Bthi[(size_t)nr * KD + kg] = h;
            g_Btlo[(size_t)nr * KD + kg] = l;
        }
}

// ---------------------------------------------------------------------------
// K0b: rest (NO dynamic smem -> high occupancy).
//   blocks [0,8):  cbias[0:256] — lanes = 32 coalesced c, 8 warps split j,
//                  unroll 16 (MLP 16), smem reduce.
//   blocks [8,..): ms/us/add rows of Bt, cbias[256:289], W2t split
// ---------------------------------------------------------------------------
__global__ __launch_bounds__(256) void k_pre_rest(
    const float* __restrict__ Wm, const float* __restrict__ bm,
    const float* __restrict__ Wu, const float* __restrict__ bu,
    const float* __restrict__ W1, const float* __restrict__ b1,
    const float* __restrict__ W2)
{
    __shared__ float red[8][32];
    int bid = blockIdx.x;
    int tid = threadIdx.x;

    if (bid < 8) {
        int cl = tid & 31, jp = tid >> 5;     // lane -> c (coalesced), warp -> j chunk
        int c = bid * 32 + cl;
        float p = 0.f;
        int j0 = jp * 64;
        #pragma unroll 16
        for (int i = 0; i < 64; i++) {
            int j = j0 + i;
            float bv = (j < 256) ? bm[j] : bu[j - 256];
            p += bv * W1[j * 256 + c];
        }
        red[jp][cl] = p;
        __syncthreads();
        if (jp == 0) {
            float s = b1[c];
            #pragma unroll
            for (int q = 0; q < 8; q++) s += red[q][cl];
            g_cbias[c] = s;
        }
        return;
    }

    int t = (bid - 8) * 256 + tid;
    if (t < KD * 16) {
        int k = t >> 4, d = t & 15;
        float s = 0.f;
        __nv_bfloat16 h, l;
        if (k < 512) {
            #pragma unroll
            for (int i = 0; i < 16; i++) s += Wm[k * 257 + i * 16 + d];
            split2(s, h, l);
            g_Bthi[(size_t)(256 + d) * KD + k] = h;
            g_Btlo[(size_t)(256 + d) * KD + k] = l;
            if (d == 0) {
                split2(Wm[k * 257 + 256], h, l);
                g_Bthi[(size_t)288 * KD + k] = h;
                g_Btlo[(size_t)288 * KD + k] = l;
            }
        } else {
            int ku = k - 512;
            #pragma unroll
            for (int i = 0; i < 16; i++) s += Wu[ku * 257 + i * 16 + d];
            split2(s, h, l);
            g_Bthi[(size_t)(272 + d) * KD + k] = h;
            g_Btlo[(size_t)(272 + d) * KD + k] = l;
            if (d == 0) {
                split2(Wu[ku * 257 + 256], h, l);
                g_Bthi[(size_t)288 * KD + k] = h;
                g_Btlo[(size_t)288 * KD + k] = l;
            }
        }
        return;
    }
    int c = t - KD * 16;
    if (c < 33) {
        int cc = 256 + c;
        float v;
        if (cc < 272) {
            int d = cc - 256; v = 0.f;
            #pragma unroll
            for (int i = 0; i < 16; i++) v += bm[i * 16 + d];
        } else if (cc < 288) {
            int d = cc - 272; v = 0.f;
            #pragma unroll
            for (int i = 0; i < 16; i++) v += bu[i * 16 + d];
        } else {
            v = bm[256] + bu[256];
        }
        g_cbias[cc] = v;
        return;
    }
    int j = c - 33;
    if (j < H2D * H1D) {
        int r = j >> 8, cc = j & 255;        // W2t[r][cc] = W2[cc][r]
        __nv_bfloat16 h, l;
        split2(W2[cc * H2D + r], h, l);
        g_W2thi[j] = h; g_W2tlo[j] = l;
    }
}

// ---------------------------------------------------------------------------
// K1: FUSED main + tail.
// Phase 1 (main): C[16384,320] = A[16384,1024 fp32] (x) Bt(hi/lo)^T, 3 terms,
//   128 CTAs, 512 thr (16 warps 4Mx4N, warp 32x80), CK=64, 2-stage.
// Phase 2 (tail, same CTA): h1(128x256) held in SMEM as bf16 hi/lo; W2t hi/lo
//   streamed via cp.async; 128x128x768 GEMM (warp 32x32); relu·W3 + FM + out.
// ---------------------------------------------------------------------------
#define CK         64
#define NCHUNK     16
#define AHI_OFF    0
#define ALO_OFF    16384
#define BHI_OFF    32768
#define BLO_OFF    73728
#define MAIN_STAGE 114688                     // 16+16+40+40 KB
#define SMEM_MAIN  (2 * MAIN_STAGE)           // 224 KB

// Tail overlay offsets (valid after main loop's final sync):
#define TH_HI   0                             // 4 chunks x 16KB = 64KB
#define TH_LO   65536                         // 64KB
#define TW2     131072                        // 2 bufs x 32KB (hi 16K + lo 16K)
#define TMSUS   196608                        // 128 rows x 36 floats = 18KB
#define TB2     215040                        // 128 floats
#define TW3     215552                        // 128 floats
#define TPS     216064                        // 128 x 4 floats

static __device__ __forceinline__ void ldg_a(float4* p, int ch, int m0, int t,
                                             const float* __restrict__ mv,
                                             const float* __restrict__ uv)
{
    int kc = ch * CK;
    const float* base = (kc < 512) ? (mv + kc) : (uv + kc - 512);
    #pragma unroll
    for (int l = 0; l < 4; l++) {
        int f = t + l * 512;
        int row = f >> 4, q = f & 15;
        p[l] = *reinterpret_cast<const float4*>(base + (size_t)(m0 + row) * 512 + q * 4);
    }
}

static __device__ __forceinline__ void sts_a(const float4* p, uint32_t stg, int t)
{
    #pragma unroll
    for (int l = 0; l < 4; l++) {
        int f = t + l * 512;
        int row = f >> 4, q = f & 15;
        __nv_bfloat16 h0, l0, h1, l1, h2, l2, h3, l3;
        split2(p[l].x, h0, l0); split2(p[l].y, h1, l1);
        split2(p[l].z, h2, l2); split2(p[l].w, h3, l3);
        uint32_t hi0 = pack_bf2(h0, h1), hi1 = pack_bf2(h2, h3);
        uint32_t lo0 = pack_bf2(l0, l1), lo1 = pack_bf2(l2, l3);
        uint32_t off = SWZ(row * 128 + q * 8);
        asm volatile("st.shared.v2.b32 [%0], {%1,%2};"
                     :: "r"(stg + AHI_OFF + off), "r"(hi0), "r"(hi1) : "memory");
        asm volatile("st.shared.v2.b32 [%0], {%1,%2};"
                     :: "r"(stg + ALO_OFF + off), "r"(lo0), "r"(lo1) : "memory");
    }
}

static __device__ __forceinline__ void cp_b(uint32_t stg, int ch, int t)
{
    int kc = ch * CK;
    #pragma unroll
    for (int l = 0; l < 10; l++) {
        int f = t + l * 512;                  // 0..5119: 2560 hi + 2560 lo units
        int lobuf = f >= 2560;
        int fr = lobuf ? f - 2560 : f;
        int row = fr >> 3, u = fr & 7;
        const __nv_bfloat16* src = (lobuf ? g_Btlo : g_Bthi) + (size_t)row * KD + kc + u * 8;
        cp16(stg + (lobuf ? BLO_OFF : BHI_OFF) + SWZ(row * 128 + u * 16), src);
    }
}

static __device__ __forceinline__ void cp_w2(uint32_t sb, int buf, int ch, int t)
{
    int kc = ch * 64;
    #pragma unroll
    for (int l = 0; l < 4; l++) {
        int f = t + l * 512;                  // 0..2047: 1024 hi + 1024 lo
        int lo = f >= 1024;
        int fr = lo ? f - 1024 : f;
        int row = fr >> 3, u = fr & 7;
        const __nv_bfloat16* src = (lo ? g_W2tlo : g_W2thi) + row * H1D + kc + u * 8;
        cp16(sb + TW2 + buf * 32768 + (lo ? 16384 : 0) + SWZ(row * 128 + u * 16), src);
    }
}

static __device__ __forceinline__ void chunk_ks(uint32_t stg, int ks,
                                                int wm, int wn,
                                                int a_row, int a_koff,
                                                int b_row, int b_koff,
                                                float c[2][10][4])
{
    uint32_t ahi[2][4], alo[2][4];
    #pragma unroll
    for (int mt = 0; mt < 2; mt++) {
        uint32_t ra = SWZ((wm * 32 + mt * 16 + a_row) * 128 + ks * 32 + a_koff);
        LDSM4(ahi[mt][0], ahi[mt][1], ahi[mt][2], ahi[mt][3], stg + AHI_OFF + ra);
        LDSM4(alo[mt][0], alo[mt][1], alo[mt][2], alo[mt][3], stg + ALO_OFF + ra);
    }
    #pragma unroll
    for (int jp = 0; jp < 5; jp++) {
        uint32_t rb = SWZ((wn * 80 + jp * 16 + b_row) * 128 + ks * 32 + b_koff);
        uint32_t b0[2], b1[2];
        LDSM4(b0[0], b0[1], b1[0], b1[1], stg + BHI_OFF + rb);   // Bhi
        #pragma unroll
        for (int mt = 0; mt < 2; mt++) {
            MMA16816(c[mt][2 * jp],     ahi[mt], b0);
            MMA16816(c[mt][2 * jp + 1], ahi[mt], b1);
            MMA16816(c[mt][2 * jp],     alo[mt], b0);
            MMA16816(c[mt][2 * jp + 1], alo[mt], b1);
        }
        LDSM4(b0[0], b0[1], b1[0], b1[1], stg + BLO_OFF + rb);   // Blo
        #pragma unroll
        for (int mt = 0; mt < 2; mt++) {
            MMA16816(c[mt][2 * jp],     ahi[mt], b0);
            MMA16816(c[mt][2 * jp + 1], ahi[mt], b1);
        }
    }
}

__global__ __launch_bounds__(512, 1) void k_mma_main(
    const float* __restrict__ mv, const float* __restrict__ uv,
    const float* __restrict__ b2, const float* __restrict__ W3,
    const float* __restrict__ b3, float* __restrict__ out)
{
    extern __shared__ char smem[];
    uint32_t sb = smem_u32(smem);
    int t = threadIdx.x;
    int lane = t & 31, wid = t >> 5;
    int wm = wid & 3, wn = wid >> 2;          // 4M x 4N warps
    int m0 = blockIdx.x * 128;

    float c[2][10][4];
    #pragma unroll
    for (int i = 0; i < 2; i++)
        #pragma unroll
        for (int j = 0; j < 10; j++)
            #pragma unroll
            for (int q = 0; q < 4; q++) c[i][j][q] = 0.f;

    int a_row  = (lane & 15);
    int a_koff = (lane >> 4) * 16;
    int b_row  = ((lane >> 4) & 1) * 8 + (lane & 7);
    int b_koff = ((lane >> 3) & 1) * 16;

    // ---------------- Phase 1: main GEMM ----------------
    {
        float4 q0[4];
        ldg_a(q0, 0, m0, t, mv, uv);
        cp_b(sb, 0, t); CP_COMMIT();
        sts_a(q0, sb, t);
    }

    float4 pf[4];
    #pragma unroll 1
    for (int ic = 0; ic < NCHUNK; ic++) {
        bool pfv = (ic + 1 < NCHUNK);
        if (pfv) ldg_a(pf, ic + 1, m0, t, mv, uv);
        CP_WAIT0();
        __syncthreads();
        uint32_t nstg = sb + ((ic + 1) & 1) * MAIN_STAGE;
        if (pfv) cp_b(nstg, ic + 1, t);
        CP_COMMIT();

        uint32_t stg = sb + (ic & 1) * MAIN_STAGE;
        chunk_ks(stg, 0, wm, wn, a_row, a_koff, b_row, b_koff, c);
        chunk_ks(stg, 1, wm, wn, a_row, a_koff, b_row, b_koff, c);
        if (pfv) sts_a(pf, nstg, t);
        chunk_ks(stg, 2, wm, wn, a_row, a_koff, b_row, b_koff, c);
        chunk_ks(stg, 3, wm, wn, a_row, a_koff, b_row, b_koff, c);
    }

    __syncthreads();   // all warps done reading stage smem -> overlay is safe

    // ---------------- Epilogue: bias+relu, H -> SMEM, ms/us/add -> SMEM ----
    float b2v = 0.f, w3v = 0.f;
    if (t < 128) { b2v = b2[t]; w3v = W3[t]; }   // prefetch (LDG latency hidden)

    #pragma unroll
    for (int mt = 0; mt < 2; mt++) {
        #pragma unroll
        for (int half = 0; half < 2; half++) {
            int r = wm * 32 + mt * 16 + (lane >> 2) + half * 8;  // CTA-local row
            #pragma unroll
            for (int j = 0; j < 10; j++) {
                int n = wn * 80 + j * 8 + (lane & 3) * 2;
                float v0 = c[mt][j][half * 2 + 0] + g_cbias[n < NOUT ? n : 0];
                float v1 = c[mt][j][half * 2 + 1] + g_cbias[(n + 1) < NOUT ? (n + 1) : 0];
                if (n < 256) {
                    v0 = fmaxf(v0, 0.f); v1 = fmaxf(v1, 0.f);
                    __nv_bfloat16 h0, l0, h1, l1;
                    split2(v0, h0, l0); split2(v1, h1, l1);
                    uint32_t off = (n >> 6) * 16384 + SWZ(r * 128 + (n & 63) * 2);
                    *reinterpret_cast<uint32_t*>(smem + TH_HI + off) = pack_bf2(h0, h1);
                    *reinterpret_cast<uint32_t*>(smem + TH_LO + off) = pack_bf2(l0, l1);
                } else {
                    float* msus = reinterpret_cast<float*>(smem + TMSUS) + r * 36;
                    #pragma unroll
                    for (int e = 0; e < 2; e++) {
                        int ne = n + e;
                        float ve = e ? v1 : v0;
                        if (ne < 272)       msus[ne - 256] = ve;        // ms
                        else if (ne < 288)  msus[16 + ne - 272] = ve;   // us
                        else if (ne == 288) msus[32] = ve;              // add
                    }
                }
            }
        }
    }
    if (t < 128) {
        reinterpret_cast<float*>(smem + TB2)[t] = b2v;
        reinterpret_cast<float*>(smem + TW3)[t] = w3v;
    }
    cp_w2(sb, 0, 0, t); CP_COMMIT();

    // ---------------- Phase 2: tail GEMM (warp = 32 rows x 32 cols) --------
    float a2[2][4][4];
    #pragma unroll
    for (int i = 0; i < 2; i++)
        #pragma unroll
        for (int j = 0; j < 4; j++)
            #pragma unroll
            for (int q = 0; q < 4; q++) a2[i][j][q] = 0.f;

    #pragma unroll 1
    for (int ch = 0; ch < 4; ch++) {
        CP_WAIT0();
        __syncthreads();            // W2(ch) ready; prior readers of other buf done
        if (ch + 1 < 4) cp_w2(sb, (ch + 1) & 1, ch + 1, t);
        CP_COMMIT();

        uint32_t hh  = sb + TH_HI + ch * 16384;
        uint32_t hl  = sb + TH_LO + ch * 16384;
        uint32_t w2h = sb + TW2 + (ch & 1) * 32768;
        uint32_t w2l = w2h + 16384;
        #pragma unroll
        for (int ks = 0; ks < 4; ks++) {
            uint32_t ahi[2][4], alo[2][4];
            #pragma unroll
            for (int mt = 0; mt < 2; mt++) {
                uint32_t ra = SWZ((wm * 32 + mt * 16 + a_row) * 128 + ks * 32 + a_koff);
                LDSM4(ahi[mt][0], ahi[mt][1], ahi[mt][2], ahi[mt][3], hh + ra);
                LDSM4(alo[mt][0], alo[mt][1], alo[mt][2], alo[mt][3], hl + ra);
            }
            uint32_t bh[4][2], bl[4][2];
            #pragma unroll
            for (int jp = 0; jp < 2; jp++) {
                uint32_t rb = SWZ((wn * 32 + jp * 16 + b_row) * 128 + ks * 32 + b_koff);
                LDSM4(bh[2 * jp][0], bh[2 * jp][1], bh[2 * jp + 1][0], bh[2 * jp + 1][1], w2h + rb);
                LDSM4(bl[2 * jp][0], bl[2 * jp][1], bl[2 * jp + 1][0], bl[2 * jp + 1][1], w2l + rb);
            }
            #pragma unroll
            for (int mt = 0; mt < 2; mt++)
                #pragma unroll
                for (int j = 0; j < 4; j++) {
                    MMA16816(a2[mt][j], ahi[mt], bh[j]);
                    MMA16816(a2[mt][j], alo[mt], bh[j]);
                    MMA16816(a2[mt][j], ahi[mt], bl[j]);
                }
        }
    }

    // relu(+b2)·w3 over this warp's 32 cols, lane-reduce, cross-warp via smem.
    const float* b2s = reinterpret_cast<const float*>(smem + TB2);
    const float* w3s = reinterpret_cast<const float*>(smem + TW3);
    float* ps = reinterpret_cast<float*>(smem + TPS);
    #pragma unroll
    for (int mt = 0; mt < 2; mt++) {
        float p0 = 0.f, p1 = 0.f;
        #pragma unroll
        for (int j = 0; j < 4; j++) {
            int n = wn * 32 + j * 8 + (lane & 3) * 2;
            p0 += fmaxf(a2[mt][j][0] + b2s[n],     0.f) * w3s[n];
            p0 += fmaxf(a2[mt][j][1] + b2s[n + 1], 0.f) * w3s[n + 1];
            p1 += fmaxf(a2[mt][j][2] + b2s[n],     0.f) * w3s[n];
            p1 += fmaxf(a2[mt][j][3] + b2s[n + 1], 0.f) * w3s[n + 1];
        }
        p0 += __shfl_xor_sync(0xFFFFFFFF, p0, 1);
        p0 += __shfl_xor_sync(0xFFFFFFFF, p0, 2);
        p1 += __shfl_xor_sync(0xFFFFFFFF, p1, 1);
        p1 += __shfl_xor_sync(0xFFFFFFFF, p1, 2);
        if ((lane & 3) == 0) {
            int r0 = wm * 32 + mt * 16 + (lane >> 2);
            ps[r0 * 4 + wn]       = p0;
            ps[(r0 + 8) * 4 + wn] = p1;
        }
    }
    __syncthreads();

    if (t < 128) {
        const float* msus = reinterpret_cast<const float*>(smem + TMSUS) + t * 36;
        float s = b3[0] + msus[32] + ps[t * 4] + ps[t * 4 + 1] + ps[t * 4 + 2] + ps[t * 4 + 3];
        #pragma unroll
        for (int i = 0; i < 16; i++) s += msus[i] * msus[16 + i];
        out[m0 + t] = s;
    }
}

// ---------------------------------------------------------------------------
extern "C" void kernel_launch(void* const* d_in, const int* in_sizes, int n_in,
                              void* d_out, int out_size)
{
    const float* mv = (const float*)d_in[0];
    const float* uv = (const float*)d_in[1];
    const float* Wm = (const float*)d_in[2];
    const float* bm = (const float*)d_in[3];
    const float* Wu = (const float*)d_in[4];
    const float* bu = (const float*)d_in[5];
    const float* W1 = (const float*)d_in[6];
    const float* b1 = (const float*)d_in[7];
    const float* W2 = (const float*)d_in[8];
    const float* b2 = (const float*)d_in[9];
    const float* W3 = (const float*)d_in[10];
    const float* b3 = (const float*)d_in[11];
    float* out = (float*)d_out;

    cudaFuncSetAttribute(k_pre_combine, cudaFuncAttributeMaxDynamicSharedMemorySize, PRE_SMEM);
    cudaFuncSetAttribute(k_mma_main,    cudaFuncAttributeMaxDynamicSharedMemorySize, SMEM_MAIN);

    // Precompute: zero-smem rest blocks (coalesced, high-MLP bias) + big-smem
    // combine blocks.
    k_pre_rest<<<8 + (KD * 16 + 33 + H2D * H1D + 255) / 256, 256>>>(Wm, bm, Wu, bu, W1, b1, W2);
    k_pre_combine<<<128, 256, PRE_SMEM>>>(Wm, Wu, W1);

    // Fused main + tail GEMM, one wave of 128 CTAs.
    k_mma_main<<<BATCH / 128, 512, SMEM_MAIN>>>(mv, uv, b2, W3, b3, out);
}